// round 12
// baseline (speedup 1.0000x reference)
#include <cuda_runtime.h>
#include <cuda_bf16.h>
#include <cstdint>

#define BATCH 64
#define D 256
#define NTOK 4095
#define NCH 20             // 12 (layer1 K=768) + 4 (layer2) + 4 (layer3), K-chunk = 64

__device__ float g_node_val[2047 * BATCH * D];
__device__ __align__(256) uint4 g_W[NCH * 4096];   // 1.25 MB, fragment-major
// tail activations, indexed by GLOBAL node id (0..254): 4096 uint4 (hi 2048 | lo 2048)
__device__ __align__(256) uint4 g_actA[255 * 4096];
__device__ __align__(256) uint4 g_actB[255 * 4096];
// per-(layer,node) completion counters, 3 x 255
__device__ int g_flags[765];

// ---------------- SMEM layout ----------------
#define ASLOT   16896
#define ALO     8448
#define AFLO    32768
#define BIASOFF 65536
#define RPTROFF 68608
#define SMEM_TOTAL 70144
// tail: l1 path uses As ring [0,33792) + rowptr @33792 (192 ptrs); l23 path stage 2x16KB + rowptr @32768
#define T1_RPTR   33792
#define T2_RPTR   32768
#define TAIL_SMEM 35328

// ---------------- helpers ----------------
__device__ __forceinline__ uint32_t smem_u32(const void* p) {
    uint32_t a;
    asm("{ .reg .u64 t; cvta.to.shared.u64 t, %1; cvt.u32.u64 %0, t; }" : "=r"(a) : "l"(p));
    return a;
}
__device__ __forceinline__ void cp_async16(uint32_t dst, const void* src) {
    asm volatile("cp.async.cg.shared.global [%0], [%1], 16;" :: "r"(dst), "l"(src) : "memory");
}
__device__ __forceinline__ void cp_commit() { asm volatile("cp.async.commit_group;" ::: "memory"); }
template<int N> __device__ __forceinline__ void cp_wait() {
    asm volatile("cp.async.wait_group %0;" :: "n"(N) : "memory");
}
__device__ __forceinline__ void mma16816(float d[4], uint32_t a0, uint32_t a1, uint32_t a2, uint32_t a3,
                                         uint32_t b0, uint32_t b1) {
    asm volatile("mma.sync.aligned.m16n8k16.row.col.f32.bf16.bf16.f32 "
                 "{%0,%1,%2,%3}, {%4,%5,%6,%7}, {%8,%9}, {%0,%1,%2,%3};"
                 : "+f"(d[0]), "+f"(d[1]), "+f"(d[2]), "+f"(d[3])
                 : "r"(a0), "r"(a1), "r"(a2), "r"(a3), "r"(b0), "r"(b1));
}
__device__ __forceinline__ uint32_t b2u(__nv_bfloat162 v) { return *reinterpret_cast<uint32_t*>(&v); }
__device__ __forceinline__ uint32_t splith(float x, float y, uint32_t& l) {
    __nv_bfloat162 hh = __floats2bfloat162_rn(x, y);
    __nv_bfloat162 ll = __floats2bfloat162_rn(x - __bfloat162float(hh.x),
                                              y - __bfloat162float(hh.y));
    l = b2u(ll);
    return b2u(hh);
}
__device__ __forceinline__ float elu1(float v) { return v > 0.f ? v : (__expf(v) - 1.f); }

// -------- weight prep --------
__global__ void prep_weights(const float* __restrict__ W_in,
                             const float* __restrict__ W1,
                             const float* __restrict__ W2) {
    int idx = blockIdx.x * 256 + threadIdx.x;
    if (idx >= NCH * 4096) return;
    int lane = idx & 31;
    int jt   = (idx >> 5) & 31;
    int s    = (idx >> 10) & 3;
    int gcw  = idx >> 12;
    int n  = jt * 8 + (lane >> 2);
    int tg = lane & 3;
    const float* Wsrc; int K, kb;
    if (gcw < 12)      { Wsrc = W_in; K = 768; kb = gcw * 64; }
    else if (gcw < 16) { Wsrc = W1;   K = 256; kb = (gcw - 12) * 64; }
    else               { Wsrc = W2;   K = 256; kb = (gcw - 16) * 64; }
    int k0 = kb + s * 16 + tg * 2;
    uint32_t l0, l1;
    uint32_t h0 = splith(Wsrc[n * K + k0],     Wsrc[n * K + k0 + 1], l0);
    uint32_t h1 = splith(Wsrc[n * K + k0 + 8], Wsrc[n * K + k0 + 9], l1);
    g_W[idx] = make_uint4(h0, h1, l0, l1);
}

__global__ void reset_flags() {
    int i = blockIdx.x * 256 + threadIdx.x;
    if (i < 765) g_flags[i] = 0;
}

__device__ __forceinline__ void ldgB(uint4 B[4], int gc, int ks, int wn, int lane) {
    const uint4* wp = g_W + (((gc * 4 + ks) * 32) + wn * 4) * 32 + lane;
    B[0] = wp[0];
    B[1] = wp[32];
    B[2] = wp[64];
    B[3] = wp[96];
}

// ================= fused 3-layer kernel (levels >= 256) — R8-proven, unchanged =================
__global__ void __launch_bounds__(256, 2)
level_kernel(const int* __restrict__ tokens, const float* __restrict__ E,
             const float* __restrict__ b_in, const float* __restrict__ b1,
             const float* __restrict__ b2, float* __restrict__ d_out, int level)
{
    extern __shared__ char smem[];
    float* bias = (float*)(smem + BIASOFF);
    const float** rowptr = (const float**)(smem + RPTROFF);
    char* As = smem;
    char* Af = smem;

    const int tid  = threadIdx.x;
    const int wn   = tid >> 5;
    const int lane = tid & 31;
    const int g    = lane >> 2;
    const int tig  = lane & 3;
    const int node = level - 1 + blockIdx.x;

    const int gc_  = tid >> 4;
    const int grg  = (tid >> 2) & 3;
    const int gtig = tid & 3;
    const int gr0  = (gc_ >> 2) * 16 + grg;
    const int gs   = gc_ & 3;

    bias[tid]       = b_in[tid];
    bias[256 + tid] = b1[tid];
    bias[512 + tid] = b2[tid];
    if (tid < 64) {
        int b = tid;
        rowptr[tid] = E + (size_t)tokens[b * NTOK + node] * D;
        if (level == 1024) {
            rowptr[64 + tid]  = E + (size_t)tokens[b * NTOK + 2 * node + 1] * D;
            rowptr[128 + tid] = E + (size_t)tokens[b * NTOK + 2 * node + 2] * D;
        } else {
            rowptr[64 + tid]  = g_node_val + ((size_t)(2 * node + 1) * BATCH + b) * D;
            rowptr[128 + tid] = g_node_val + ((size_t)(2 * node + 2) * BATCH + b) * D;
        }
    }

    float acc[4][4][4];
    #pragma unroll
    for (int i = 0; i < 4; ++i)
        #pragma unroll
        for (int j = 0; j < 4; ++j)
            #pragma unroll
            for (int q = 0; q < 4; ++q) acc[i][j][q] = 0.f;

    __syncthreads();

    {
        const float* pr0 = rowptr[gr0];
        const float* pr1 = rowptr[gr0 + 8];
        const float* pr2 = rowptr[gr0 + 4];
        const float* pr3 = rowptr[gr0 + 12];
        int kb = gs * 16 + gtig * 2;
        float2 a0 = *(const float2*)(pr0 + kb),     a1 = *(const float2*)(pr1 + kb);
        float2 a2 = *(const float2*)(pr0 + kb + 8), a3 = *(const float2*)(pr1 + kb + 8);
        float2 c0 = *(const float2*)(pr2 + kb),     c1 = *(const float2*)(pr3 + kb);
        float2 c2 = *(const float2*)(pr2 + kb + 8), c3 = *(const float2*)(pr3 + kb + 8);
        uint4 h1v, l1v, h2v, l2v;
        h1v.x = splith(a0.x, a0.y, l1v.x); h1v.y = splith(a1.x, a1.y, l1v.y);
        h1v.z = splith(a2.x, a2.y, l1v.z); h1v.w = splith(a3.x, a3.y, l1v.w);
        h2v.x = splith(c0.x, c0.y, l2v.x); h2v.y = splith(c1.x, c1.y, l2v.y);
        h2v.z = splith(c2.x, c2.y, l2v.z); h2v.w = splith(c3.x, c3.y, l2v.w);
        char* b1p = As + gc_ * 528 + (grg * 4 + gtig) * 16;
        char* b2p = As + gc_ * 528 + ((grg + 4) * 4 + gtig) * 16;
        *(uint4*)b1p = h1v; *(uint4*)(b1p + ALO) = l1v;
        *(uint4*)b2p = h2v; *(uint4*)(b2p + ALO) = l2v;
    }
    __syncthreads();

    for (int gcc = 0; gcc < 12; ++gcc) {
        const int slot = gcc & 1;
        const bool doGather = (gcc + 1 < 12);

        float2 a0, a1, a2, a3, c0, c1, c2, c3;
        if (doGather) {
            int gn = gcc + 1;
            int seg = gn >> 2;
            int kb = (gn & 3) * 64 + gs * 16 + gtig * 2;
            const float* pr0 = rowptr[seg * 64 + gr0];
            const float* pr1 = rowptr[seg * 64 + gr0 + 8];
            const float* pr2 = rowptr[seg * 64 + gr0 + 4];
            const float* pr3 = rowptr[seg * 64 + gr0 + 12];
            a0 = *(const float2*)(pr0 + kb);     a1 = *(const float2*)(pr1 + kb);
            a2 = *(const float2*)(pr0 + kb + 8); a3 = *(const float2*)(pr1 + kb + 8);
            c0 = *(const float2*)(pr2 + kb);     c1 = *(const float2*)(pr3 + kb);
            c2 = *(const float2*)(pr2 + kb + 8); c3 = *(const float2*)(pr3 + kb + 8);
        }

        const char* ab = As + slot * ASLOT;
        uint4 B[4];
        ldgB(B, gcc, 0, wn, lane);
        #pragma unroll
        for (int ks = 0; ks < 4; ++ks) {
            uint4 Bn[4];
            if (ks < 3) ldgB(Bn, gcc, ks + 1, wn, lane);
            #pragma unroll
            for (int half = 0; half < 2; ++half) {
                uint4 Ahi[2], Alo[2];
                #pragma unroll
                for (int i2 = 0; i2 < 2; ++i2) {
                    const char* p = ab + ((half * 2 + i2) * 4 + ks) * 528 + lane * 16;
                    Ahi[i2] = *(const uint4*)p;
                    Alo[i2] = *(const uint4*)(p + ALO);
                }
                #pragma unroll
                for (int j = 0; j < 4; ++j)
                    #pragma unroll
                    for (int i2 = 0; i2 < 2; ++i2) {
                        float* a = acc[half * 2 + i2][j];
                        mma16816(a, Ahi[i2].x, Ahi[i2].y, Ahi[i2].z, Ahi[i2].w, B[j].x, B[j].y);
                        mma16816(a, Ahi[i2].x, Ahi[i2].y, Ahi[i2].z, Ahi[i2].w, B[j].z, B[j].w);
                        mma16816(a, Alo[i2].x, Alo[i2].y, Alo[i2].z, Alo[i2].w, B[j].x, B[j].y);
                    }
            }
            if (ks < 3) { B[0] = Bn[0]; B[1] = Bn[1]; B[2] = Bn[2]; B[3] = Bn[3]; }
        }

        if (doGather) {
            uint4 h1v, l1v, h2v, l2v;
            h1v.x = splith(a0.x, a0.y, l1v.x); h1v.y = splith(a1.x, a1.y, l1v.y);
            h1v.z = splith(a2.x, a2.y, l1v.z); h1v.w = splith(a3.x, a3.y, l1v.w);
            h2v.x = splith(c0.x, c0.y, l2v.x); h2v.y = splith(c1.x, c1.y, l2v.y);
            h2v.z = splith(c2.x, c2.y, l2v.z); h2v.w = splith(c3.x, c3.y, l2v.w);
            char* sb = As + (slot ^ 1) * ASLOT + gc_ * 528;
            char* b1p = sb + (grg * 4 + gtig) * 16;
            char* b2p = sb + ((grg + 4) * 4 + gtig) * 16;
            *(uint4*)b1p = h1v; *(uint4*)(b1p + ALO) = l1v;
            *(uint4*)b2p = h2v; *(uint4*)(b2p + ALO) = l2v;
        }
        __syncthreads();
    }

    #pragma unroll
    for (int i = 0; i < 4; ++i) {
        #pragma unroll
        for (int jp = 0; jp < 2; ++jp) {
            uint4 hv, lv;
            #pragma unroll
            for (int u = 0; u < 2; ++u) {
                int j = 2 * jp + u;
                int cb = wn * 32 + j * 8 + tig * 2;
                float v0 = elu1(acc[i][j][0] + bias[cb]);
                float v1 = elu1(acc[i][j][1] + bias[cb + 1]);
                float v2 = elu1(acc[i][j][2] + bias[cb]);
                float v3 = elu1(acc[i][j][3] + bias[cb + 1]);
                if (u == 0) { hv.x = splith(v0, v1, lv.x); hv.y = splith(v2, v3, lv.y); }
                else        { hv.z = splith(v0, v1, lv.z); hv.w = splith(v2, v3, lv.w); }
                acc[i][j][0] = acc[i][j][1] = acc[i][j][2] = acc[i][j][3] = 0.f;
            }
            char* p = Af + ((i * 16 + wn * 2 + jp) * 32 + lane) * 16;
            *(uint4*)p = hv;
            *(uint4*)(p + AFLO) = lv;
        }
    }
    __syncthreads();

    #pragma unroll 1
    for (int layer = 1; layer <= 2; ++layer) {
        const int gbase = (layer == 1) ? 12 : 16;
        #pragma unroll 1
        for (int c = 0; c < 4; ++c) {
            const int gcw = gbase + c;
            uint4 B[4];
            ldgB(B, gcw, 0, wn, lane);
            #pragma unroll
            for (int ks = 0; ks < 4; ++ks) {
                uint4 Bn[4];
                if (ks < 3) ldgB(Bn, gcw, ks + 1, wn, lane);
                int sg = c * 4 + ks;
                #pragma unroll
                for (int half = 0; half < 2; ++half) {
                    uint4 Ahi[2], Alo[2];
                    #pragma unroll
                    for (int i2 = 0; i2 < 2; ++i2) {
                        const char* p = Af + (((half * 2 + i2) * 16 + sg) * 32 + lane) * 16;
                        Ahi[i2] = *(const uint4*)p;
                        Alo[i2] = *(const uint4*)(p + AFLO);
                    }
                    #pragma unroll
                    for (int j = 0; j < 4; ++j)
                        #pragma unroll
                        for (int i2 = 0; i2 < 2; ++i2) {
                            float* a = acc[half * 2 + i2][j];
                            mma16816(a, Ahi[i2].x, Ahi[i2].y, Ahi[i2].z, Ahi[i2].w, B[j].x, B[j].y);
                            mma16816(a, Ahi[i2].x, Ahi[i2].y, Ahi[i2].z, Ahi[i2].w, B[j].z, B[j].w);
                            mma16816(a, Alo[i2].x, Alo[i2].y, Alo[i2].z, Alo[i2].w, B[j].x, B[j].y);
                        }
                }
                if (ks < 3) { B[0] = Bn[0]; B[1] = Bn[1]; B[2] = Bn[2]; B[3] = Bn[3]; }
            }
        }

        if (layer == 1) {
            __syncthreads();
            #pragma unroll
            for (int i = 0; i < 4; ++i) {
                #pragma unroll
                for (int jp = 0; jp < 2; ++jp) {
                    uint4 hv, lv;
                    #pragma unroll
                    for (int u = 0; u < 2; ++u) {
                        int j = 2 * jp + u;
                        int cb = wn * 32 + j * 8 + tig * 2;
                        float v0 = elu1(acc[i][j][0] + bias[256 + cb]);
                        float v1 = elu1(acc[i][j][1] + bias[256 + cb + 1]);
                        float v2 = elu1(acc[i][j][2] + bias[256 + cb]);
                        float v3 = elu1(acc[i][j][3] + bias[256 + cb + 1]);
                        if (u == 0) { hv.x = splith(v0, v1, lv.x); hv.y = splith(v2, v3, lv.y); }
                        else        { hv.z = splith(v0, v1, lv.z); hv.w = splith(v2, v3, lv.w); }
                        acc[i][j][0] = acc[i][j][1] = acc[i][j][2] = acc[i][j][3] = 0.f;
                    }
                    char* p = Af + ((i * 16 + wn * 2 + jp) * 32 + lane) * 16;
                    *(uint4*)p = hv;
                    *(uint4*)(p + AFLO) = lv;
                }
            }
            __syncthreads();
        }
    }

    #pragma unroll
    for (int i = 0; i < 4; ++i) {
        int r_g  = i * 16 + g;
        int r_g8 = r_g + 8;
        const float* e0p = rowptr[r_g];
        const float* e1p = rowptr[r_g8];
        #pragma unroll
        for (int j = 0; j < 4; ++j) {
            int cb = wn * 32 + j * 8 + tig * 2;
            float b0v = bias[512 + cb], b1v = bias[512 + cb + 1];
            float2 e0 = *(const float2*)(e0p + cb);
            float2 e1 = *(const float2*)(e1p + cb);
            float2 o0 = make_float2(acc[i][j][0] + b0v + e0.x, acc[i][j][1] + b1v + e0.y);
            float2 o1 = make_float2(acc[i][j][2] + b0v + e1.x, acc[i][j][3] + b1v + e1.y);
            *(float2*)(g_node_val + ((size_t)node * BATCH + r_g)  * D + cb) = o0;
            *(float2*)(g_node_val + ((size_t)node * BATCH + r_g8) * D + cb) = o1;
        }
    }
}

// ================= tail: ALL levels <= 128, ONE launch, per-node flag dataflow =================
__global__ void __launch_bounds__(256, 2)
tail_all(const int* __restrict__ tokens, const float* __restrict__ E,
         const float* __restrict__ b_in, const float* __restrict__ b1,
         const float* __restrict__ b2, float* __restrict__ d_out)
{
    extern __shared__ char smem[];
    const int tid  = threadIdx.x;
    const int wn   = tid >> 5;
    const int lane = tid & 31;
    const int g    = lane >> 2;

    // decode bid -> (level, layer, node, cs4); bid order: level 128..1, within level l1,l2,l3
    int b = blockIdx.x;
    int level = 128;
    while (b >= level * 12) { b -= level * 12; level >>= 1; }
    const int lay  = b / (level * 4);
    const int r    = b - lay * (level * 4);
    const int nloc = r >> 2;
    const int cs4  = r & 3;
    const int node = level - 1 + nloc;
    const int jt   = cs4 * 8 + wn;

    // ---- dependency wait ----
    if (tid == 0) {
        if (lay == 0) {
            if (level < 128) {
                volatile int* f1 = g_flags + 2 * 255 + (2 * node + 1);
                volatile int* f2 = g_flags + 2 * 255 + (2 * node + 2);
                while (*f1 < 4) __nanosleep(64);
                while (*f2 < 4) __nanosleep(64);
            }
        } else {
            volatile int* f = g_flags + (lay - 1) * 255 + node;
            while (*f < 4) __nanosleep(64);
        }
    }
    __syncthreads();
    __threadfence();

    float acc[4][4];
    #pragma unroll
    for (int i = 0; i < 4; ++i)
        #pragma unroll
        for (int q = 0; q < 4; ++q) acc[i][q] = 0.f;

    if (lay == 0) {
        // ================= layer 1: K=768 gather path =================
        const float** rowptr = (const float**)(smem + T1_RPTR);
        char* As = smem;
        const int tig  = lane & 3;
        const int gc_  = tid >> 4;
        const int grg  = (tid >> 2) & 3;
        const int gtig = tid & 3;
        const int gr0  = (gc_ >> 2) * 16 + grg;
        const int gs   = gc_ & 3;

        if (tid < 64) {
            int bb = tid;
            rowptr[tid]       = E + (size_t)tokens[bb * NTOK + node] * D;
            rowptr[64 + tid]  = g_node_val + ((size_t)(2 * node + 1) * BATCH + bb) * D;
            rowptr[128 + tid] = g_node_val + ((size_t)(2 * node + 2) * BATCH + bb) * D;
        }
        __syncthreads();
        {
            const float* pr0 = rowptr[gr0];
            const float* pr1 = rowptr[gr0 + 8];
            const float* pr2 = rowptr[gr0 + 4];
            const float* pr3 = rowptr[gr0 + 12];
            int kb = gs * 16 + gtig * 2;
            float2 a0 = *(const float2*)(pr0 + kb),     a1 = *(const float2*)(pr1 + kb);
            float2 a2 = *(const float2*)(pr0 + kb + 8), a3 = *(const float2*)(pr1 + kb + 8);
            float2 c0 = *(const float2*)(pr2 + kb),     c1 = *(const float2*)(pr3 + kb);
            float2 c2 = *(const float2*)(pr2 + kb + 8), c3 = *(const float2*)(pr3 + kb + 8);
            uint4 h1v, l1v, h2v, l2v;
            h1v.x = splith(a0.x, a0.y, l1v.x); h1v.y = splith(a1.x, a1.y, l1v.y);
            h1v.z = splith(a2.x, a2.y, l1v.z); h1v.w = splith(a3.x, a3.y, l1v.w);
            h2v.x = splith(c0.x, c0.y, l2v.x); h2v.y = splith(c1.x, c1.y, l2v.y);
            h2v.z = splith(c2.x, c2.y, l2v.z); h2v.w = splith(c3.x, c3.y, l2v.w);
            char* b1p = As + gc_ * 528 + (grg * 4 + gtig) * 16;
            char* b2p = As + gc_ * 528 + ((grg + 4) * 4 + gtig) * 16;
            *(uint4*)b1p = h1v; *(uint4*)(b1p + ALO) = l1v;
            *(uint4*)b2p = h2v; *(uint4*)(b2p + ALO) = l2v;
        }
        __syncthreads();

        for (int gcc = 0; gcc < 12; ++gcc) {
            const int slot = gcc & 1;
            const bool doGather = (gcc + 1 < 12);

            float2 a0, a1, a2, a3, c0, c1, c2, c3;
            if (doGather) {
                int gn = gcc + 1;
                int seg = gn >> 2;
                int kb = (gn & 3) * 64 + gs * 16 + gtig * 2;
                const float* pr0 = rowptr[seg * 64 + gr0];
                const float* pr1 = rowptr[seg * 64 + gr0 + 8];
                const float* pr2 = rowptr[seg * 64 + gr0 + 4];
                const float* pr3 = rowptr[seg * 64 + gr0 + 12];
                a0 = *(const float2*)(pr0 + kb);     a1 = *(const float2*)(pr1 + kb);
                a2 = *(const float2*)(pr0 + kb + 8); a3 = *(const float2*)(pr1 + kb + 8);
                c0 = *(const float2*)(pr2 + kb);     c1 = *(const float2*)(pr3 + kb);
                c2 = *(const float2*)(pr2 + kb + 8); c3 = *(const float2*)(pr3 + kb + 8);
            }

            const char* ab = As + slot * ASLOT;
            const uint4* wp = g_W + ((size_t)(gcc * 4) * 32 + jt) * 32 + lane;
            uint4 B = wp[0];
            #pragma unroll
            for (int ks = 0; ks < 4; ++ks) {
                uint4 Bn;
                if (ks < 3) Bn = wp[(ks + 1) * 1024];
                #pragma unroll
                for (int i = 0; i < 4; ++i) {
                    const char* p = ab + (i * 4 + ks) * 528 + lane * 16;
                    uint4 Ahi = *(const uint4*)p;
                    uint4 Alo = *(const uint4*)(p + ALO);
                    mma16816(acc[i], Ahi.x, Ahi.y, Ahi.z, Ahi.w, B.x, B.y);
                    mma16816(acc[i], Ahi.x, Ahi.y, Ahi.z, Ahi.w, B.z, B.w);
                    mma16816(acc[i], Alo.x, Alo.y, Alo.z, Alo.w, B.x, B.y);
                }
                if (ks < 3) B = Bn;
            }

            if (doGather) {
                uint4 h1v, l1v, h2v, l2v;
                h1v.x = splith(a0.x, a0.y, l1v.x); h1v.y = splith(a1.x, a1.y, l1v.y);
                h1v.z = splith(a2.x, a2.y, l1v.z); h1v.w = splith(a3.x, a3.y, l1v.w);
                h2v.x = splith(c0.x, c0.y, l2v.x); h2v.y = splith(c1.x, c1.y, l2v.y);
                h2v.z = splith(c2.x, c2.y, l2v.z); h2v.w = splith(c3.x, c3.y, l2v.w);
                char* sb = As + (slot ^ 1) * ASLOT + gc_ * 528;
                char* b1p = sb + (grg * 4 + gtig) * 16;
                char* b2p = sb + ((grg + 4) * 4 + gtig) * 16;
                *(uint4*)b1p = h1v; *(uint4*)(b1p + ALO) = l1v;
                *(uint4*)b2p = h2v; *(uint4*)(b2p + ALO) = l2v;
            }
            __syncthreads();
        }

        // epilogue -> g_actA[node]
        {
            int cb = cs4 * 64 + wn * 8 + tig * 2;
            float b0v = b_in[cb], b1v = b_in[cb + 1];
            int sg = cs4 * 4 + (wn >> 1);
            int hoff = (wn & 1) * 8;
            #pragma unroll
            for (int i = 0; i < 4; ++i) {
                float v0 = elu1(acc[i][0] + b0v);
                float v1 = elu1(acc[i][1] + b1v);
                float v2 = elu1(acc[i][2] + b0v);
                float v3 = elu1(acc[i][3] + b1v);
                uint32_t lx, ly;
                uint32_t hx = splith(v0, v1, lx);
                uint32_t hy = splith(v2, v3, ly);
                char* dst = (char*)(g_actA + (size_t)node * 4096 + (i * 16 + sg) * 32 + lane) + hoff;
                *(uint2*)dst = make_uint2(hx, hy);
                *(uint2*)(dst + 2048 * 16) = make_uint2(lx, ly);
            }
        }
    } else {
        // ================= layers 2/3: K=256 from g_act =================
        const float** rowptr = (const float**)(smem + T2_RPTR);
        const uint32_t sb = smem_u32(smem);
        const int tig = tid & 3;
        const int gbase = (lay == 2) ? 16 : 12;
        const uint4* actSrc = ((lay == 2) ? g_actB : g_actA) + (size_t)node * 4096;

        if (lay == 2 && tid < 64)
            rowptr[tid] = E + (size_t)tokens[tid * NTOK + node] * D;

        const int cidx = tid;
        #pragma unroll
        for (int rr = 0; rr < 4; ++rr) {
            int idx = rr * 256 + cidx;
            int part = idx >> 9, w = idx & 511, i = w >> 7, off = w & 127;
            cp_async16(sb + idx * 16, (const void*)(actSrc + part * 2048 + i * 512 + off));
        }
        cp_commit();

        #pragma unroll 1
        for (int c = 0; c < 4; ++c) {
            if (c + 1 < 4) {
                uint32_t dstb = sb + ((c + 1) & 1) * 16384;
                #pragma unroll
                for (int rr = 0; rr < 4; ++rr) {
                    int idx = rr * 256 + cidx;
                    int part = idx >> 9, w = idx & 511, i = w >> 7, off = w & 127;
                    cp_async16(dstb + idx * 16,
                               (const void*)(actSrc + part * 2048 + i * 512 + (c + 1) * 128 + off));
                }
                cp_commit();
                cp_wait<1>();
            } else {
                cp_wait<0>();
            }
            __syncthreads();

            const uint4* slot = (const uint4*)(smem + (c & 1) * 16384);
            const uint4* wp = g_W + ((size_t)((gbase + c) * 4) * 32 + jt) * 32 + lane;
            uint4 B = wp[0];
            #pragma unroll
            for (int ks = 0; ks < 4; ++ks) {
                uint4 Bn;
                if (ks < 3) Bn = wp[(ks + 1) * 1024];
                #pragma unroll
                for (int i = 0; i < 4; ++i) {
                    uint4 Ahi = slot[i * 128 + ks * 32 + lane];
                    uint4 Alo = slot[512 + i * 128 + ks * 32 + lane];
                    mma16816(acc[i], Ahi.x, Ahi.y, Ahi.z, Ahi.w, B.x, B.y);
                    mma16816(acc[i], Ahi.x, Ahi.y, Ahi.z, Ahi.w, B.z, B.w);
                    mma16816(acc[i], Alo.x, Alo.y, Alo.z, Alo.w, B.x, B.y);
                }
                if (ks < 3) B = Bn;
            }
            __syncthreads();
        }

        int cb = cs4 * 64 + wn * 8 + tig * 2;
        if (lay == 1) {
            float b0v = b1[cb], b1v = b1[cb + 1];
            int sg = cs4 * 4 + (wn >> 1);
            int hoff = (wn & 1) * 8;
            #pragma unroll
            for (int i = 0; i < 4; ++i) {
                float v0 = elu1(acc[i][0] + b0v);
                float v1 = elu1(acc[i][1] + b1v);
                float v2 = elu1(acc[i][2] + b0v);
                float v3 = elu1(acc[i][3] + b1v);
                uint32_t lx, ly;
                uint32_t hx = splith(v0, v1, lx);
                uint32_t hy = splith(v2, v3, ly);
                char* dst = (char*)(g_actB + (size_t)node * 4096 + (i * 16 + sg) * 32 + lane) + hoff;
                *(uint2*)dst = make_uint2(hx, hy);
                *(uint2*)(dst + 2048 * 16) = make_uint2(lx, ly);
            }
        } else {
            float b0v = b2[cb], b1v = b2[cb + 1];
            #pragma unroll
            for (int i = 0; i < 4; ++i) {
                int r0 = i * 16 + g, r1 = r0 + 8;
                float2 e0 = *(const float2*)(rowptr[r0] + cb);
                float2 e1 = *(const float2*)(rowptr[r1] + cb);
                float2 o0 = make_float2(acc[i][0] + b0v + e0.x, acc[i][1] + b1v + e0.y);
                float2 o1 = make_float2(acc[i][2] + b0v + e1.x, acc[i][3] + b1v + e1.y);
                if (level == 1) {
                    *(float2*)(d_out + (size_t)r0 * D + cb) = o0;
                    *(float2*)(d_out + (size_t)r1 * D + cb) = o1;
                } else {
                    *(float2*)(g_node_val + ((size_t)node * BATCH + r0) * D + cb) = o0;
                    *(float2*)(g_node_val + ((size_t)node * BATCH + r1) * D + cb) = o1;
                }
            }
        }
    }

    // ---- release: data visible, then arrive ----
    __threadfence();
    __syncthreads();
    if (tid == 0) atomicAdd(&g_flags[lay * 255 + node], 1);
}

extern "C" void kernel_launch(void* const* d_in, const int* in_sizes, int n_in,
                              void* d_out, int out_size) {
    const int*   tokens = (const int*)d_in[0];
    const float* E      = (const float*)d_in[1];
    const float* W_in   = (const float*)d_in[2];
    const float* b_in   = (const float*)d_in[3];
    const float* W1     = (const float*)d_in[4];
    const float* b1     = (const float*)d_in[5];
    const float* W2     = (const float*)d_in[6];
    const float* b2     = (const float*)d_in[7];
    float* out = (float*)d_out;

    cudaFuncSetAttribute(level_kernel, cudaFuncAttributeMaxDynamicSharedMemorySize, SMEM_TOTAL);
    cudaFuncSetAttribute(tail_all,     cudaFuncAttributeMaxDynamicSharedMemorySize, TAIL_SMEM);

    prep_weights<<<(NCH * 4096) / 256, 256>>>(W_in, W1, W2);
    reset_flags<<<3, 256>>>();

    for (int level = 1024; level >= 256; level >>= 1)
        level_kernel<<<level, 256, SMEM_TOTAL>>>(tokens, E, b_in, b1, b2, out, level);

    // all levels <= 128 in one dataflow launch: 12 * (128+64+...+1) = 3060 blocks
    tail_all<<<3060, 256, TAIL_SMEM>>>(tokens, E, b_in, b1, b2, out);
}

// round 13
// speedup vs baseline: 1.3856x; 1.3856x over previous
#include <cuda_runtime.h>
#include <cuda_fp16.h>
#include <cstdint>

#define BATCH 64
#define D 256
#define NTOK 4095
#define NCH 20             // 12 (layer1 K=768) + 4 (layer2) + 4 (layer3), K-chunk = 64

__device__ float g_node_val[2047 * BATCH * D];
__device__ __align__(256) uint4 g_W[NCH * 4096];   // {Whi pair0, Whi pair1, Wlo pair0, Wlo pair1}
// tail activations (fp16, hi only): per node 2048 uint4
__device__ __align__(256) uint4 g_actA[128 * 2048];
__device__ __align__(256) uint4 g_actB[128 * 2048];

// ---------------- SMEM layout ----------------
// fused kernel: As ring 2x8448 aliases Af [0,32768); bias @32768; rowptr @35840
#define ASLOT   8448
#define BIASOFF 32768
#define RPTROFF 35840
#define SMEM_TOTAL 37376
// tail L1: As ring [0,16896) + rowptr @16896 (192 ptrs)
#define T1_RPTR   16896
#define T1_SMEM   18432
// tail L2/3: stage 2 x 8KB + rowptr @16384 (64 ptrs)
#define T2_RPTR   16384
#define T2_SMEM   16896

// ---------------- helpers ----------------
__device__ __forceinline__ uint32_t smem_u32(const void* p) {
    uint32_t a;
    asm("{ .reg .u64 t; cvta.to.shared.u64 t, %1; cvt.u32.u64 %0, t; }" : "=r"(a) : "l"(p));
    return a;
}
__device__ __forceinline__ void cp_async16(uint32_t dst, const void* src) {
    asm volatile("cp.async.cg.shared.global [%0], [%1], 16;" :: "r"(dst), "l"(src) : "memory");
}
__device__ __forceinline__ void cp_commit() { asm volatile("cp.async.commit_group;" ::: "memory"); }
template<int N> __device__ __forceinline__ void cp_wait() {
    asm volatile("cp.async.wait_group %0;" :: "n"(N) : "memory");
}
__device__ __forceinline__ void mma16816(float d[4], uint32_t a0, uint32_t a1, uint32_t a2, uint32_t a3,
                                         uint32_t b0, uint32_t b1) {
    asm volatile("mma.sync.aligned.m16n8k16.row.col.f32.f16.f16.f32 "
                 "{%0,%1,%2,%3}, {%4,%5,%6,%7}, {%8,%9}, {%0,%1,%2,%3};"
                 : "+f"(d[0]), "+f"(d[1]), "+f"(d[2]), "+f"(d[3])
                 : "r"(a0), "r"(a1), "r"(a2), "r"(a3), "r"(b0), "r"(b1));
}
__device__ __forceinline__ uint32_t h2u2(float x, float y) {
    __half2 h = __floats2half2_rn(x, y);
    return *reinterpret_cast<uint32_t*>(&h);
}
__device__ __forceinline__ uint32_t hsplit(float x, float y, uint32_t& lo) {
    __half2 h = __floats2half2_rn(x, y);
    float hx = __half2float(__low2half(h));
    float hy = __half2float(__high2half(h));
    __half2 l = __floats2half2_rn(x - hx, y - hy);
    lo = *reinterpret_cast<uint32_t*>(&l);
    return *reinterpret_cast<uint32_t*>(&h);
}
__device__ __forceinline__ float elu1(float v) { return v > 0.f ? v : (__expf(v) - 1.f); }

// -------- weight prep: fp32 -> fp16 hi/lo, frag-major K64 chunks --------
__global__ void prep_weights(const float* __restrict__ W_in,
                             const float* __restrict__ W1,
                             const float* __restrict__ W2) {
    int idx = blockIdx.x * 256 + threadIdx.x;
    if (idx >= NCH * 4096) return;
    int lane = idx & 31;
    int jt   = (idx >> 5) & 31;
    int s    = (idx >> 10) & 3;
    int gcw  = idx >> 12;
    int n  = jt * 8 + (lane >> 2);
    int tg = lane & 3;
    const float* Wsrc; int K, kb;
    if (gcw < 12)      { Wsrc = W_in; K = 768; kb = gcw * 64; }
    else if (gcw < 16) { Wsrc = W1;   K = 256; kb = (gcw - 12) * 64; }
    else               { Wsrc = W2;   K = 256; kb = (gcw - 16) * 64; }
    int k0 = kb + s * 16 + tg * 2;
    uint32_t l0, l1;
    uint32_t h0 = hsplit(Wsrc[n * K + k0],     Wsrc[n * K + k0 + 1], l0);
    uint32_t h1 = hsplit(Wsrc[n * K + k0 + 8], Wsrc[n * K + k0 + 9], l1);
    g_W[idx] = make_uint4(h0, h1, l0, l1);
}

__device__ __forceinline__ void ldgB(uint4 B[4], int gc, int ks, int wn, int lane) {
    const uint4* wp = g_W + (((gc * 4 + ks) * 32) + wn * 4) * 32 + lane;
    B[0] = wp[0];
    B[1] = wp[32];
    B[2] = wp[64];
    B[3] = wp[96];
}

// ================= fused 3-layer kernel (levels >= 256) =================
__global__ void __launch_bounds__(256, 2)
level_kernel(const int* __restrict__ tokens, const float* __restrict__ E,
             const float* __restrict__ b_in, const float* __restrict__ b1,
             const float* __restrict__ b2, float* __restrict__ d_out, int level)
{
    extern __shared__ char smem[];
    float* bias = (float*)(smem + BIASOFF);
    const float** rowptr = (const float**)(smem + RPTROFF);
    char* As = smem;
    char* Af = smem;

    const int tid  = threadIdx.x;
    const int wn   = tid >> 5;
    const int lane = tid & 31;
    const int g    = lane >> 2;
    const int tig  = lane & 3;
    const int node = level - 1 + blockIdx.x;

    const int gc_  = tid >> 4;
    const int grg  = (tid >> 2) & 3;
    const int gtig = tid & 3;
    const int gr0  = (gc_ >> 2) * 16 + grg;
    const int gs   = gc_ & 3;

    bias[tid]       = b_in[tid];
    bias[256 + tid] = b1[tid];
    bias[512 + tid] = b2[tid];
    if (tid < 64) {
        int b = tid;
        rowptr[tid] = E + (size_t)tokens[b * NTOK + node] * D;
        if (level == 1024) {
            rowptr[64 + tid]  = E + (size_t)tokens[b * NTOK + 2 * node + 1] * D;
            rowptr[128 + tid] = E + (size_t)tokens[b * NTOK + 2 * node + 2] * D;
        } else {
            rowptr[64 + tid]  = g_node_val + ((size_t)(2 * node + 1) * BATCH + b) * D;
            rowptr[128 + tid] = g_node_val + ((size_t)(2 * node + 2) * BATCH + b) * D;
        }
    }

    float acc[4][4][4];
    #pragma unroll
    for (int i = 0; i < 4; ++i)
        #pragma unroll
        for (int j = 0; j < 4; ++j)
            #pragma unroll
            for (int q = 0; q < 4; ++q) acc[i][j][q] = 0.f;

    __syncthreads();

    {   // A(0) gather (fp16, hi only)
        const float* pr0 = rowptr[gr0];
        const float* pr1 = rowptr[gr0 + 8];
        const float* pr2 = rowptr[gr0 + 4];
        const float* pr3 = rowptr[gr0 + 12];
        int kb = gs * 16 + gtig * 2;
        float2 a0 = *(const float2*)(pr0 + kb),     a1 = *(const float2*)(pr1 + kb);
        float2 a2 = *(const float2*)(pr0 + kb + 8), a3 = *(const float2*)(pr1 + kb + 8);
        float2 c0 = *(const float2*)(pr2 + kb),     c1 = *(const float2*)(pr3 + kb);
        float2 c2 = *(const float2*)(pr2 + kb + 8), c3 = *(const float2*)(pr3 + kb + 8);
        uint4 h1v = make_uint4(h2u2(a0.x, a0.y), h2u2(a1.x, a1.y), h2u2(a2.x, a2.y), h2u2(a3.x, a3.y));
        uint4 h2v = make_uint4(h2u2(c0.x, c0.y), h2u2(c1.x, c1.y), h2u2(c2.x, c2.y), h2u2(c3.x, c3.y));
        *(uint4*)(As + gc_ * 528 + (grg * 4 + gtig) * 16)       = h1v;
        *(uint4*)(As + gc_ * 528 + ((grg + 4) * 4 + gtig) * 16) = h2v;
    }
    __syncthreads();

    for (int gcc = 0; gcc < 12; ++gcc) {
        const int slot = gcc & 1;
        const bool doGather = (gcc + 1 < 12);

        float2 a0, a1, a2, a3, c0, c1, c2, c3;
        if (doGather) {
            int gn = gcc + 1;
            int seg = gn >> 2;
            int kb = (gn & 3) * 64 + gs * 16 + gtig * 2;
            const float* pr0 = rowptr[seg * 64 + gr0];
            const float* pr1 = rowptr[seg * 64 + gr0 + 8];
            const float* pr2 = rowptr[seg * 64 + gr0 + 4];
            const float* pr3 = rowptr[seg * 64 + gr0 + 12];
            a0 = *(const float2*)(pr0 + kb);     a1 = *(const float2*)(pr1 + kb);
            a2 = *(const float2*)(pr0 + kb + 8); a3 = *(const float2*)(pr1 + kb + 8);
            c0 = *(const float2*)(pr2 + kb);     c1 = *(const float2*)(pr3 + kb);
            c2 = *(const float2*)(pr2 + kb + 8); c3 = *(const float2*)(pr3 + kb + 8);
        }

        const char* ab = As + slot * ASLOT;
        uint4 B[4];
        ldgB(B, gcc, 0, wn, lane);
        #pragma unroll
        for (int ks = 0; ks < 4; ++ks) {
            uint4 Bn[4];
            if (ks < 3) ldgB(Bn, gcc, ks + 1, wn, lane);
            #pragma unroll
            for (int half = 0; half < 2; ++half) {
                uint4 A0 = *(const uint4*)(ab + ((half * 2 + 0) * 4 + ks) * 528 + lane * 16);
                uint4 A1 = *(const uint4*)(ab + ((half * 2 + 1) * 4 + ks) * 528 + lane * 16);
                #pragma unroll
                for (int j = 0; j < 4; ++j) {
                    float* p0 = acc[half * 2 + 0][j];
                    float* p1 = acc[half * 2 + 1][j];
                    mma16816(p0, A0.x, A0.y, A0.z, A0.w, B[j].x, B[j].y);
                    mma16816(p0, A0.x, A0.y, A0.z, A0.w, B[j].z, B[j].w);
                    mma16816(p1, A1.x, A1.y, A1.z, A1.w, B[j].x, B[j].y);
                    mma16816(p1, A1.x, A1.y, A1.z, A1.w, B[j].z, B[j].w);
                }
            }
            if (ks < 3) { B[0] = Bn[0]; B[1] = Bn[1]; B[2] = Bn[2]; B[3] = Bn[3]; }
        }

        if (doGather) {
            uint4 h1v = make_uint4(h2u2(a0.x, a0.y), h2u2(a1.x, a1.y), h2u2(a2.x, a2.y), h2u2(a3.x, a3.y));
            uint4 h2v = make_uint4(h2u2(c0.x, c0.y), h2u2(c1.x, c1.y), h2u2(c2.x, c2.y), h2u2(c3.x, c3.y));
            char* sb = As + (slot ^ 1) * ASLOT + gc_ * 528;
            *(uint4*)(sb + (grg * 4 + gtig) * 16)       = h1v;
            *(uint4*)(sb + ((grg + 4) * 4 + gtig) * 16) = h2v;
        }
        __syncthreads();
    }

    // mid epilogue 1: bias + ELU -> Af (fp16)
    #pragma unroll
    for (int i = 0; i < 4; ++i) {
        #pragma unroll
        for (int jp = 0; jp < 2; ++jp) {
            uint4 hv;
            #pragma unroll
            for (int u = 0; u < 2; ++u) {
                int j = 2 * jp + u;
                int cb = wn * 32 + j * 8 + tig * 2;
                float v0 = elu1(acc[i][j][0] + bias[cb]);
                float v1 = elu1(acc[i][j][1] + bias[cb + 1]);
                float v2 = elu1(acc[i][j][2] + bias[cb]);
                float v3 = elu1(acc[i][j][3] + bias[cb + 1]);
                if (u == 0) { hv.x = h2u2(v0, v1); hv.y = h2u2(v2, v3); }
                else        { hv.z = h2u2(v0, v1); hv.w = h2u2(v2, v3); }
                acc[i][j][0] = acc[i][j][1] = acc[i][j][2] = acc[i][j][3] = 0.f;
            }
            *(uint4*)(Af + ((i * 16 + wn * 2 + jp) * 32 + lane) * 16) = hv;
        }
    }
    __syncthreads();

    // layers 2 & 3
    #pragma unroll 1
    for (int layer = 1; layer <= 2; ++layer) {
        const int gbase = (layer == 1) ? 12 : 16;
        #pragma unroll 1
        for (int c = 0; c < 4; ++c) {
            const int gcw = gbase + c;
            uint4 B[4];
            ldgB(B, gcw, 0, wn, lane);
            #pragma unroll
            for (int ks = 0; ks < 4; ++ks) {
                uint4 Bn[4];
                if (ks < 3) ldgB(Bn, gcw, ks + 1, wn, lane);
                int sg = c * 4 + ks;
                #pragma unroll
                for (int half = 0; half < 2; ++half) {
                    uint4 A0 = *(const uint4*)(Af + (((half * 2 + 0) * 16 + sg) * 32 + lane) * 16);
                    uint4 A1 = *(const uint4*)(Af + (((half * 2 + 1) * 16 + sg) * 32 + lane) * 16);
                    #pragma unroll
                    for (int j = 0; j < 4; ++j) {
                        float* p0 = acc[half * 2 + 0][j];
                        float* p1 = acc[half * 2 + 1][j];
                        mma16816(p0, A0.x, A0.y, A0.z, A0.w, B[j].x, B[j].y);
                        mma16816(p0, A0.x, A0.y, A0.z, A0.w, B[j].z, B[j].w);
                        mma16816(p1, A1.x, A1.y, A1.z, A1.w, B[j].x, B[j].y);
                        mma16816(p1, A1.x, A1.y, A1.z, A1.w, B[j].z, B[j].w);
                    }
                }
                if (ks < 3) { B[0] = Bn[0]; B[1] = Bn[1]; B[2] = Bn[2]; B[3] = Bn[3]; }
            }
        }

        if (layer == 1) {
            __syncthreads();
            #pragma unroll
            for (int i = 0; i < 4; ++i) {
                #pragma unroll
                for (int jp = 0; jp < 2; ++jp) {
                    uint4 hv;
                    #pragma unroll
                    for (int u = 0; u < 2; ++u) {
                        int j = 2 * jp + u;
                        int cb = wn * 32 + j * 8 + tig * 2;
                        float v0 = elu1(acc[i][j][0] + bias[256 + cb]);
                        float v1 = elu1(acc[i][j][1] + bias[256 + cb + 1]);
                        float v2 = elu1(acc[i][j][2] + bias[256 + cb]);
                        float v3 = elu1(acc[i][j][3] + bias[256 + cb + 1]);
                        if (u == 0) { hv.x = h2u2(v0, v1); hv.y = h2u2(v2, v3); }
                        else        { hv.z = h2u2(v0, v1); hv.w = h2u2(v2, v3); }
                        acc[i][j][0] = acc[i][j][1] = acc[i][j][2] = acc[i][j][3] = 0.f;
                    }
                    *(uint4*)(Af + ((i * 16 + wn * 2 + jp) * 32 + lane) * 16) = hv;
                }
            }
            __syncthreads();
        }
    }

    // final epilogue
    #pragma unroll
    for (int i = 0; i < 4; ++i) {
        int r_g  = i * 16 + g;
        int r_g8 = r_g + 8;
        const float* e0p = rowptr[r_g];
        const float* e1p = rowptr[r_g8];
        #pragma unroll
        for (int j = 0; j < 4; ++j) {
            int cb = wn * 32 + j * 8 + tig * 2;
            float b0v = bias[512 + cb], b1v = bias[512 + cb + 1];
            float2 e0 = *(const float2*)(e0p + cb);
            float2 e1 = *(const float2*)(e1p + cb);
            float2 o0 = make_float2(acc[i][j][0] + b0v + e0.x, acc[i][j][1] + b1v + e0.y);
            float2 o1 = make_float2(acc[i][j][2] + b0v + e1.x, acc[i][j][3] + b1v + e1.y);
            *(float2*)(g_node_val + ((size_t)node * BATCH + r_g)  * D + cb) = o0;
            *(float2*)(g_node_val + ((size_t)node * BATCH + r_g8) * D + cb) = o1;
        }
    }
}

// ================= tail path (levels <= 128): per-layer, N split 4-ways =================

__global__ void __launch_bounds__(256, 2)
tail_l1(const int* __restrict__ tokens, const float* __restrict__ E,
        const float* __restrict__ b_in, int level)
{
    extern __shared__ char smem[];
    const float** rowptr = (const float**)(smem + T1_RPTR);
    char* As = smem;

    const int tid  = threadIdx.x;
    const int wn   = tid >> 5;
    const int lane = tid & 31;
    const int tig  = lane & 3;
    const int nloc = blockIdx.x >> 2;
    const int cs4  = blockIdx.x & 3;
    const int node = level - 1 + nloc;
    const int jt   = cs4 * 8 + wn;

    const int gc_  = tid >> 4;
    const int grg  = (tid >> 2) & 3;
    const int gtig = tid & 3;
    const int gr0  = (gc_ >> 2) * 16 + grg;
    const int gs   = gc_ & 3;

    if (tid < 64) {
        int b = tid;
        rowptr[tid]       = E + (size_t)tokens[b * NTOK + node] * D;
        rowptr[64 + tid]  = g_node_val + ((size_t)(2 * node + 1) * BATCH + b) * D;
        rowptr[128 + tid] = g_node_val + ((size_t)(2 * node + 2) * BATCH + b) * D;
    }

    float acc[4][4];
    #pragma unroll
    for (int i = 0; i < 4; ++i)
        #pragma unroll
        for (int q = 0; q < 4; ++q) acc[i][q] = 0.f;

    __syncthreads();
    {
        const float* pr0 = rowptr[gr0];
        const float* pr1 = rowptr[gr0 + 8];
        const float* pr2 = rowptr[gr0 + 4];
        const float* pr3 = rowptr[gr0 + 12];
        int kb = gs * 16 + gtig * 2;
        float2 a0 = *(const float2*)(pr0 + kb),     a1 = *(const float2*)(pr1 + kb);
        float2 a2 = *(const float2*)(pr0 + kb + 8), a3 = *(const float2*)(pr1 + kb + 8);
        float2 c0 = *(const float2*)(pr2 + kb),     c1 = *(const float2*)(pr3 + kb);
        float2 c2 = *(const float2*)(pr2 + kb + 8), c3 = *(const float2*)(pr3 + kb + 8);
        uint4 h1v = make_uint4(h2u2(a0.x, a0.y), h2u2(a1.x, a1.y), h2u2(a2.x, a2.y), h2u2(a3.x, a3.y));
        uint4 h2v = make_uint4(h2u2(c0.x, c0.y), h2u2(c1.x, c1.y), h2u2(c2.x, c2.y), h2u2(c3.x, c3.y));
        *(uint4*)(As + gc_ * 528 + (grg * 4 + gtig) * 16)       = h1v;
        *(uint4*)(As + gc_ * 528 + ((grg + 4) * 4 + gtig) * 16) = h2v;
    }
    __syncthreads();

    for (int gcc = 0; gcc < 12; ++gcc) {
        const int slot = gcc & 1;
        const bool doGather = (gcc + 1 < 12);

        float2 a0, a1, a2, a3, c0, c1, c2, c3;
        if (doGather) {
            int gn = gcc + 1;
            int seg = gn >> 2;
            int kb = (gn & 3) * 64 + gs * 16 + gtig * 2;
            const float* pr0 = rowptr[seg * 64 + gr0];
            const float* pr1 = rowptr[seg * 64 + gr0 + 8];
            const float* pr2 = rowptr[seg * 64 + gr0 + 4];
            const float* pr3 = rowptr[seg * 64 + gr0 + 12];
            a0 = *(const float2*)(pr0 + kb);     a1 = *(const float2*)(pr1 + kb);
            a2 = *(const float2*)(pr0 + kb + 8); a3 = *(const float2*)(pr1 + kb + 8);
            c0 = *(const float2*)(pr2 + kb);     c1 = *(const float2*)(pr3 + kb);
            c2 = *(const float2*)(pr2 + kb + 8); c3 = *(const float2*)(pr3 + kb + 8);
        }

        const char* ab = As + slot * ASLOT;
        const uint4* wp = g_W + ((size_t)(gcc * 4) * 32 + jt) * 32 + lane;
        uint4 B = wp[0];
        #pragma unroll
        for (int ks = 0; ks < 4; ++ks) {
            uint4 Bn;
            if (ks < 3) Bn = wp[(ks + 1) * 1024];
            #pragma unroll
            for (int i = 0; i < 4; ++i) {
                uint4 A0 = *(const uint4*)(ab + (i * 4 + ks) * 528 + lane * 16);
                mma16816(acc[i], A0.x, A0.y, A0.z, A0.w, B.x, B.y);
                mma16816(acc[i], A0.x, A0.y, A0.z, A0.w, B.z, B.w);
            }
            if (ks < 3) B = Bn;
        }

        if (doGather) {
            uint4 h1v = make_uint4(h2u2(a0.x, a0.y), h2u2(a1.x, a1.y), h2u2(a2.x, a2.y), h2u2(a3.x, a3.y));
            uint4 h2v = make_uint4(h2u2(c0.x, c0.y), h2u2(c1.x, c1.y), h2u2(c2.x, c2.y), h2u2(c3.x, c3.y));
            char* sb = As + (slot ^ 1) * ASLOT + gc_ * 528;
            *(uint4*)(sb + (grg * 4 + gtig) * 16)       = h1v;
            *(uint4*)(sb + ((grg + 4) * 4 + gtig) * 16) = h2v;
        }
        __syncthreads();
    }

    {
        int cb = cs4 * 64 + wn * 8 + tig * 2;
        float b0v = b_in[cb], b1v = b_in[cb + 1];
        int sg = cs4 * 4 + (wn >> 1);
        int hoff = (wn & 1) * 8;
        #pragma unroll
        for (int i = 0; i < 4; ++i) {
            float v0 = elu1(acc[i][0] + b0v);
            float v1 = elu1(acc[i][1] + b1v);
            float v2 = elu1(acc[i][2] + b0v);
            float v3 = elu1(acc[i][3] + b1v);
            char* dst = (char*)(g_actA + (size_t)nloc * 2048 + (i * 16 + sg) * 32 + lane) + hoff;
            *(uint2*)dst = make_uint2(h2u2(v0, v1), h2u2(v2, v3));
        }
    }
}

__global__ void __launch_bounds__(256, 2)
tail_l23(const int* __restrict__ tokens, const float* __restrict__ E,
         const float* __restrict__ bp, float* __restrict__ d_out, int level, int phase)
{
    extern __shared__ char smem[];
    const float** rowptr = (const float**)(smem + T2_RPTR);
    const uint32_t sb = smem_u32(smem);

    const int tid  = threadIdx.x;
    const int wn   = tid >> 5;
    const int lane = tid & 31;
    const int g    = lane >> 2;
    const int tig  = tid & 3;
    const int nloc = blockIdx.x >> 2;
    const int cs4  = blockIdx.x & 3;
    const int node = level - 1 + nloc;
    const int jt   = cs4 * 8 + wn;
    const int gbase = phase ? 16 : 12;
    const uint4* actSrc = (phase ? g_actB : g_actA) + (size_t)nloc * 2048;

    if (phase && tid < 64)
        rowptr[tid] = E + (size_t)tokens[tid * NTOK + node] * D;

    float acc[4][4];
    #pragma unroll
    for (int i = 0; i < 4; ++i)
        #pragma unroll
        for (int q = 0; q < 4; ++q) acc[i][q] = 0.f;

    // preload chunk 0: 512 uint4
    #pragma unroll
    for (int rr = 0; rr < 2; ++rr) {
        int idx = rr * 256 + tid;
        int i = idx >> 7, sgo = (idx >> 5) & 3, ln = idx & 31;
        cp_async16(sb + idx * 16, (const void*)(actSrc + (i * 16 + sgo) * 32 + ln));
    }
    cp_commit();

    #pragma unroll 1
    for (int c = 0; c < 4; ++c) {
        if (c + 1 < 4) {
            uint32_t dstb = sb + ((c + 1) & 1) * 8192;
            #pragma unroll
            for (int rr = 0; rr < 2; ++rr) {
                int idx = rr * 256 + tid;
                int i = idx >> 7, sgo = (idx >> 5) & 3, ln = idx & 31;
                cp_async16(dstb + idx * 16,
                           (const void*)(actSrc + (i * 16 + (c + 1) * 4 + sgo) * 32 + ln));
            }
            cp_commit();
            cp_wait<1>();
        } else {
            cp_wait<0>();
        }
        __syncthreads();

        const uint4* slot = (const uint4*)(smem + (c & 1) * 8192);
        const uint4* wp = g_W + ((size_t)((gbase + c) * 4) * 32 + jt) * 32 + lane;
        uint4 B = wp[0];
        #pragma unroll
        for (int ks = 0; ks < 4; ++ks) {
            uint4 Bn;
            if (ks < 3) Bn = wp[(ks + 1) * 1024];
            #pragma unroll
            for (int i = 0; i < 4; ++i) {
                uint4 A0 = slot[i * 128 + ks * 32 + lane];
                mma16816(acc[i], A0.x, A0.y, A0.z, A0.w, B.x, B.y);
                mma16816(acc[i], A0.x, A0.y, A0.z, A0.w, B.z, B.w);
            }
            if (ks < 3) B = Bn;
        }
        __syncthreads();
    }

    int cb = cs4 * 64 + wn * 8 + tig * 2;
    float b0v = bp[cb], b1v = bp[cb + 1];
    if (phase == 0) {
        int sg = cs4 * 4 + (wn >> 1);
        int hoff = (wn & 1) * 8;
        #pragma unroll
        for (int i = 0; i < 4; ++i) {
            float v0 = elu1(acc[i][0] + b0v);
            float v1 = elu1(acc[i][1] + b1v);
            float v2 = elu1(acc[i][2] + b0v);
            float v3 = elu1(acc[i][3] + b1v);
            char* dst = (char*)(g_actB + (size_t)nloc * 2048 + (i * 16 + sg) * 32 + lane) + hoff;
            *(uint2*)dst = make_uint2(h2u2(v0, v1), h2u2(v2, v3));
        }
    } else {
        #pragma unroll
        for (int i = 0; i < 4; ++i) {
            int r0 = i * 16 + g, r1 = r0 + 8;
            float2 e0 = *(const float2*)(rowptr[r0] + cb);
            float2 e1 = *(const float2*)(rowptr[r1] + cb);
            float2 o0 = make_float2(acc[i][0] + b0v + e0.x, acc[i][1] + b1v + e0.y);
            float2 o1 = make_float2(acc[i][2] + b0v + e1.x, acc[i][3] + b1v + e1.y);
            if (level == 1) {
                *(float2*)(d_out + (size_t)r0 * D + cb) = o0;
                *(float2*)(d_out + (size_t)r1 * D + cb) = o1;
            } else {
                *(float2*)(g_node_val + ((size_t)node * BATCH + r0) * D + cb) = o0;
                *(float2*)(g_node_val + ((size_t)node * BATCH + r1) * D + cb) = o1;
            }
        }
    }
}

extern "C" void kernel_launch(void* const* d_in, const int* in_sizes, int n_in,
                              void* d_out, int out_size) {
    const int*   tokens = (const int*)d_in[0];
    const float* E      = (const float*)d_in[1];
    const float* W_in   = (const float*)d_in[2];
    const float* b_in   = (const float*)d_in[3];
    const float* W1     = (const float*)d_in[4];
    const float* b1     = (const float*)d_in[5];
    const float* W2     = (const float*)d_in[6];
    const float* b2     = (const float*)d_in[7];
    float* out = (float*)d_out;

    cudaFuncSetAttribute(level_kernel, cudaFuncAttributeMaxDynamicSharedMemorySize, SMEM_TOTAL);
    cudaFuncSetAttribute(tail_l1,  cudaFuncAttributeMaxDynamicSharedMemorySize, T1_SMEM);
    cudaFuncSetAttribute(tail_l23, cudaFuncAttributeMaxDynamicSharedMemorySize, T2_SMEM);

    prep_weights<<<(NCH * 4096) / 256, 256>>>(W_in, W1, W2);

    for (int level = 1024; level >= 256; level >>= 1)
        level_kernel<<<level, 256, SMEM_TOTAL>>>(tokens, E, b_in, b1, b2, out, level);

    for (int level = 128; level >= 1; level >>= 1) {
        tail_l1 <<<level * 4, 256, T1_SMEM>>>(tokens, E, b_in, level);
        tail_l23<<<level * 4, 256, T2_SMEM>>>(tokens, E, b1, out, level, 0);
        tail_l23<<<level * 4, 256, T2_SMEM>>>(tokens, E, b2, out, level, 1);
    }
}

// round 14
// speedup vs baseline: 1.8187x; 1.3127x over previous
#include <cuda_runtime.h>
#include <cuda_fp16.h>
#include <cstdint>

#define BATCH 64
#define D 256
#define NTOK 4095
#define NCH 20             // 12 (layer1 K=768) + 4 (layer2) + 4 (layer3), K-chunk = 64

__device__ float g_node_val[2047 * BATCH * D];
__device__ __align__(256) uint2 g_W[NCH * 4096];   // fp16 {pair0, pair1}, frag-major, 640 KB
// tail activations (fp16): per node 2048 uint4
__device__ __align__(256) uint4 g_actA[128 * 2048];
__device__ __align__(256) uint4 g_actB[128 * 2048];

// ---------------- SMEM layout ----------------
// fused kernel: As ring 2x8448 aliases Af [0,32768); bias @32768; rowptr @35840
#define ASLOT   8448
#define BIASOFF 32768
#define RPTROFF 35840
#define SMEM_TOTAL 37376
// tail L1: As ring [0,16896) + rowptr @16896 (192 ptrs)
#define T1_RPTR   16896
#define T1_SMEM   18432
// tail L2/3: stage 2 x 8KB + rowptr @16384 (64 ptrs)
#define T2_RPTR   16384
#define T2_SMEM   16896

// ---------------- helpers ----------------
__device__ __forceinline__ uint32_t smem_u32(const void* p) {
    uint32_t a;
    asm("{ .reg .u64 t; cvta.to.shared.u64 t, %1; cvt.u32.u64 %0, t; }" : "=r"(a) : "l"(p));
    return a;
}
__device__ __forceinline__ void cp_async16(uint32_t dst, const void* src) {
    asm volatile("cp.async.cg.shared.global [%0], [%1], 16;" :: "r"(dst), "l"(src) : "memory");
}
__device__ __forceinline__ void cp_commit() { asm volatile("cp.async.commit_group;" ::: "memory"); }
template<int N> __device__ __forceinline__ void cp_wait() {
    asm volatile("cp.async.wait_group %0;" :: "n"(N) : "memory");
}
__device__ __forceinline__ void mma16816(float d[4], uint32_t a0, uint32_t a1, uint32_t a2, uint32_t a3,
                                         uint32_t b0, uint32_t b1) {
    asm volatile("mma.sync.aligned.m16n8k16.row.col.f32.f16.f16.f32 "
                 "{%0,%1,%2,%3}, {%4,%5,%6,%7}, {%8,%9}, {%0,%1,%2,%3};"
                 : "+f"(d[0]), "+f"(d[1]), "+f"(d[2]), "+f"(d[3])
                 : "r"(a0), "r"(a1), "r"(a2), "r"(a3), "r"(b0), "r"(b1));
}
__device__ __forceinline__ uint32_t h2u2(float x, float y) {
    __half2 h = __floats2half2_rn(x, y);
    return *reinterpret_cast<uint32_t*>(&h);
}
__device__ __forceinline__ float elu1(float v) { return v > 0.f ? v : (__expf(v) - 1.f); }

// -------- weight prep: fp32 -> fp16, frag-major K64 chunks --------
__global__ void prep_weights(const float* __restrict__ W_in,
                             const float* __restrict__ W1,
                             const float* __restrict__ W2) {
    int idx = blockIdx.x * 256 + threadIdx.x;
    if (idx >= NCH * 4096) return;
    int lane = idx & 31;
    int jt   = (idx >> 5) & 31;
    int s    = (idx >> 10) & 3;
    int gcw  = idx >> 12;
    int n  = jt * 8 + (lane >> 2);
    int tg = lane & 3;
    const float* Wsrc; int K, kb;
    if (gcw < 12)      { Wsrc = W_in; K = 768; kb = gcw * 64; }
    else if (gcw < 16) { Wsrc = W1;   K = 256; kb = (gcw - 12) * 64; }
    else               { Wsrc = W2;   K = 256; kb = (gcw - 16) * 64; }
    int k0 = kb + s * 16 + tg * 2;
    g_W[idx] = make_uint2(h2u2(Wsrc[n * K + k0],     Wsrc[n * K + k0 + 1]),
                          h2u2(Wsrc[n * K + k0 + 8], Wsrc[n * K + k0 + 9]));
}

__device__ __forceinline__ void ldgB(uint2 B[4], int gc, int ks, int wn, int lane) {
    const uint2* wp = g_W + (((gc * 4 + ks) * 32) + wn * 4) * 32 + lane;
    B[0] = wp[0];
    B[1] = wp[32];
    B[2] = wp[64];
    B[3] = wp[96];
}

// ================= fused 3-layer kernel (levels >= 256) =================
__global__ void __launch_bounds__(256, 2)
level_kernel(const int* __restrict__ tokens, const float* __restrict__ E,
             const float* __restrict__ b_in, const float* __restrict__ b1,
             const float* __restrict__ b2, float* __restrict__ d_out, int level)
{
    extern __shared__ char smem[];
    float* bias = (float*)(smem + BIASOFF);
    const float** rowptr = (const float**)(smem + RPTROFF);
    char* As = smem;
    char* Af = smem;

    const int tid  = threadIdx.x;
    const int wn   = tid >> 5;
    const int lane = tid & 31;
    const int g    = lane >> 2;
    const int tig  = lane & 3;
    const int node = level - 1 + blockIdx.x;

    const int gc_  = tid >> 4;
    const int grg  = (tid >> 2) & 3;
    const int gtig = tid & 3;
    const int gr0  = (gc_ >> 2) * 16 + grg;
    const int gs   = gc_ & 3;

    bias[tid]       = b_in[tid];
    bias[256 + tid] = b1[tid];
    bias[512 + tid] = b2[tid];
    if (tid < 64) {
        int b = tid;
        rowptr[tid] = E + (size_t)tokens[b * NTOK + node] * D;
        if (level == 1024) {
            rowptr[64 + tid]  = E + (size_t)tokens[b * NTOK + 2 * node + 1] * D;
            rowptr[128 + tid] = E + (size_t)tokens[b * NTOK + 2 * node + 2] * D;
        } else {
            rowptr[64 + tid]  = g_node_val + ((size_t)(2 * node + 1) * BATCH + b) * D;
            rowptr[128 + tid] = g_node_val + ((size_t)(2 * node + 2) * BATCH + b) * D;
        }
    }

    float acc[4][4][4];
    #pragma unroll
    for (int i = 0; i < 4; ++i)
        #pragma unroll
        for (int j = 0; j < 4; ++j)
            #pragma unroll
            for (int q = 0; q < 4; ++q) acc[i][j][q] = 0.f;

    __syncthreads();

    {   // A(0) gather (fp16)
        const float* pr0 = rowptr[gr0];
        const float* pr1 = rowptr[gr0 + 8];
        const float* pr2 = rowptr[gr0 + 4];
        const float* pr3 = rowptr[gr0 + 12];
        int kb = gs * 16 + gtig * 2;
        float2 a0 = *(const float2*)(pr0 + kb),     a1 = *(const float2*)(pr1 + kb);
        float2 a2 = *(const float2*)(pr0 + kb + 8), a3 = *(const float2*)(pr1 + kb + 8);
        float2 c0 = *(const float2*)(pr2 + kb),     c1 = *(const float2*)(pr3 + kb);
        float2 c2 = *(const float2*)(pr2 + kb + 8), c3 = *(const float2*)(pr3 + kb + 8);
        uint4 h1v = make_uint4(h2u2(a0.x, a0.y), h2u2(a1.x, a1.y), h2u2(a2.x, a2.y), h2u2(a3.x, a3.y));
        uint4 h2v = make_uint4(h2u2(c0.x, c0.y), h2u2(c1.x, c1.y), h2u2(c2.x, c2.y), h2u2(c3.x, c3.y));
        *(uint4*)(As + gc_ * 528 + (grg * 4 + gtig) * 16)       = h1v;
        *(uint4*)(As + gc_ * 528 + ((grg + 4) * 4 + gtig) * 16) = h2v;
    }
    __syncthreads();

    for (int gcc = 0; gcc < 12; ++gcc) {
        const int slot = gcc & 1;
        const bool doGather = (gcc + 1 < 12);

        float2 a0, a1, a2, a3, c0, c1, c2, c3;
        if (doGather) {
            int gn = gcc + 1;
            int seg = gn >> 2;
            int kb = (gn & 3) * 64 + gs * 16 + gtig * 2;
            const float* pr0 = rowptr[seg * 64 + gr0];
            const float* pr1 = rowptr[seg * 64 + gr0 + 8];
            const float* pr2 = rowptr[seg * 64 + gr0 + 4];
            const float* pr3 = rowptr[seg * 64 + gr0 + 12];
            a0 = *(const float2*)(pr0 + kb);     a1 = *(const float2*)(pr1 + kb);
            a2 = *(const float2*)(pr0 + kb + 8); a3 = *(const float2*)(pr1 + kb + 8);
            c0 = *(const float2*)(pr2 + kb);     c1 = *(const float2*)(pr3 + kb);
            c2 = *(const float2*)(pr2 + kb + 8); c3 = *(const float2*)(pr3 + kb + 8);
        }

        const char* ab = As + slot * ASLOT;
        uint2 B[4];
        ldgB(B, gcc, 0, wn, lane);
        #pragma unroll
        for (int ks = 0; ks < 4; ++ks) {
            uint2 Bn[4];
            if (ks < 3) ldgB(Bn, gcc, ks + 1, wn, lane);
            #pragma unroll
            for (int half = 0; half < 2; ++half) {
                uint4 A0 = *(const uint4*)(ab + ((half * 2 + 0) * 4 + ks) * 528 + lane * 16);
                uint4 A1 = *(const uint4*)(ab + ((half * 2 + 1) * 4 + ks) * 528 + lane * 16);
                #pragma unroll
                for (int j = 0; j < 4; ++j) {
                    mma16816(acc[half * 2 + 0][j], A0.x, A0.y, A0.z, A0.w, B[j].x, B[j].y);
                    mma16816(acc[half * 2 + 1][j], A1.x, A1.y, A1.z, A1.w, B[j].x, B[j].y);
                }
            }
            if (ks < 3) { B[0] = Bn[0]; B[1] = Bn[1]; B[2] = Bn[2]; B[3] = Bn[3]; }
        }

        if (doGather) {
            uint4 h1v = make_uint4(h2u2(a0.x, a0.y), h2u2(a1.x, a1.y), h2u2(a2.x, a2.y), h2u2(a3.x, a3.y));
            uint4 h2v = make_uint4(h2u2(c0.x, c0.y), h2u2(c1.x, c1.y), h2u2(c2.x, c2.y), h2u2(c3.x, c3.y));
            char* sb = As + (slot ^ 1) * ASLOT + gc_ * 528;
            *(uint4*)(sb + (grg * 4 + gtig) * 16)       = h1v;
            *(uint4*)(sb + ((grg + 4) * 4 + gtig) * 16) = h2v;
        }
        __syncthreads();
    }

    // mid epilogue 1: bias + ELU -> Af (fp16)
    #pragma unroll
    for (int i = 0; i < 4; ++i) {
        #pragma unroll
        for (int jp = 0; jp < 2; ++jp) {
            uint4 hv;
            #pragma unroll
            for (int u = 0; u < 2; ++u) {
                int j = 2 * jp + u;
                int cb = wn * 32 + j * 8 + tig * 2;
                float v0 = elu1(acc[i][j][0] + bias[cb]);
                float v1 = elu1(acc[i][j][1] + bias[cb + 1]);
                float v2 = elu1(acc[i][j][2] + bias[cb]);
                float v3 = elu1(acc[i][j][3] + bias[cb + 1]);
                if (u == 0) { hv.x = h2u2(v0, v1); hv.y = h2u2(v2, v3); }
                else        { hv.z = h2u2(v0, v1); hv.w = h2u2(v2, v3); }
                acc[i][j][0] = acc[i][j][1] = acc[i][j][2] = acc[i][j][3] = 0.f;
            }
            *(uint4*)(Af + ((i * 16 + wn * 2 + jp) * 32 + lane) * 16) = hv;
        }
    }
    __syncthreads();

    // layers 2 & 3
    #pragma unroll 1
    for (int layer = 1; layer <= 2; ++layer) {
        const int gbase = (layer == 1) ? 12 : 16;
        #pragma unroll 1
        for (int c = 0; c < 4; ++c) {
            const int gcw = gbase + c;
            uint2 B[4];
            ldgB(B, gcw, 0, wn, lane);
            #pragma unroll
            for (int ks = 0; ks < 4; ++ks) {
                uint2 Bn[4];
                if (ks < 3) ldgB(Bn, gcw, ks + 1, wn, lane);
                int sg = c * 4 + ks;
                #pragma unroll
                for (int half = 0; half < 2; ++half) {
                    uint4 A0 = *(const uint4*)(Af + (((half * 2 + 0) * 16 + sg) * 32 + lane) * 16);
                    uint4 A1 = *(const uint4*)(Af + (((half * 2 + 1) * 16 + sg) * 32 + lane) * 16);
                    #pragma unroll
                    for (int j = 0; j < 4; ++j) {
                        mma16816(acc[half * 2 + 0][j], A0.x, A0.y, A0.z, A0.w, B[j].x, B[j].y);
                        mma16816(acc[half * 2 + 1][j], A1.x, A1.y, A1.z, A1.w, B[j].x, B[j].y);
                    }
                }
                if (ks < 3) { B[0] = Bn[0]; B[1] = Bn[1]; B[2] = Bn[2]; B[3] = Bn[3]; }
            }
        }

        if (layer == 1) {
            __syncthreads();
            #pragma unroll
            for (int i = 0; i < 4; ++i) {
                #pragma unroll
                for (int jp = 0; jp < 2; ++jp) {
                    uint4 hv;
                    #pragma unroll
                    for (int u = 0; u < 2; ++u) {
                        int j = 2 * jp + u;
                        int cb = wn * 32 + j * 8 + tig * 2;
                        float v0 = elu1(acc[i][j][0] + bias[256 + cb]);
                        float v1 = elu1(acc[i][j][1] + bias[256 + cb + 1]);
                        float v2 = elu1(acc[i][j][2] + bias[256 + cb]);
                        float v3 = elu1(acc[i][j][3] + bias[256 + cb + 1]);
                        if (u == 0) { hv.x = h2u2(v0, v1); hv.y = h2u2(v2, v3); }
                        else        { hv.z = h2u2(v0, v1); hv.w = h2u2(v2, v3); }
                        acc[i][j][0] = acc[i][j][1] = acc[i][j][2] = acc[i][j][3] = 0.f;
                    }
                    *(uint4*)(Af + ((i * 16 + wn * 2 + jp) * 32 + lane) * 16) = hv;
                }
            }
            __syncthreads();
        }
    }

    // final epilogue
    #pragma unroll
    for (int i = 0; i < 4; ++i) {
        int r_g  = i * 16 + g;
        int r_g8 = r_g + 8;
        const float* e0p = rowptr[r_g];
        const float* e1p = rowptr[r_g8];
        #pragma unroll
        for (int j = 0; j < 4; ++j) {
            int cb = wn * 32 + j * 8 + tig * 2;
            float b0v = bias[512 + cb], b1v = bias[512 + cb + 1];
            float2 e0 = *(const float2*)(e0p + cb);
            float2 e1 = *(const float2*)(e1p + cb);
            float2 o0 = make_float2(acc[i][j][0] + b0v + e0.x, acc[i][j][1] + b1v + e0.y);
            float2 o1 = make_float2(acc[i][j][2] + b0v + e1.x, acc[i][j][3] + b1v + e1.y);
            *(float2*)(g_node_val + ((size_t)node * BATCH + r_g)  * D + cb) = o0;
            *(float2*)(g_node_val + ((size_t)node * BATCH + r_g8) * D + cb) = o1;
        }
    }
}

// ================= tail path (levels <= 128): per-layer, N split 4-ways =================

__global__ void __launch_bounds__(256, 2)
tail_l1(const int* __restrict__ tokens, const float* __restrict__ E,
        const float* __restrict__ b_in, int level)
{
    extern __shared__ char smem[];
    const float** rowptr = (const float**)(smem + T1_RPTR);
    char* As = smem;

    const int tid  = threadIdx.x;
    const int wn   = tid >> 5;
    const int lane = tid & 31;
    const int tig  = lane & 3;
    const int nloc = blockIdx.x >> 2;
    const int cs4  = blockIdx.x & 3;
    const int node = level - 1 + nloc;
    const int jt   = cs4 * 8 + wn;

    const int gc_  = tid >> 4;
    const int grg  = (tid >> 2) & 3;
    const int gtig = tid & 3;
    const int gr0  = (gc_ >> 2) * 16 + grg;
    const int gs   = gc_ & 3;

    if (tid < 64) {
        int b = tid;
        rowptr[tid]       = E + (size_t)tokens[b * NTOK + node] * D;
        rowptr[64 + tid]  = g_node_val + ((size_t)(2 * node + 1) * BATCH + b) * D;
        rowptr[128 + tid] = g_node_val + ((size_t)(2 * node + 2) * BATCH + b) * D;
    }

    float acc[4][4];
    #pragma unroll
    for (int i = 0; i < 4; ++i)
        #pragma unroll
        for (int q = 0; q < 4; ++q) acc[i][q] = 0.f;

    __syncthreads();
    {
        const float* pr0 = rowptr[gr0];
        const float* pr1 = rowptr[gr0 + 8];
        const float* pr2 = rowptr[gr0 + 4];
        const float* pr3 = rowptr[gr0 + 12];
        int kb = gs * 16 + gtig * 2;
        float2 a0 = *(const float2*)(pr0 + kb),     a1 = *(const float2*)(pr1 + kb);
        float2 a2 = *(const float2*)(pr0 + kb + 8), a3 = *(const float2*)(pr1 + kb + 8);
        float2 c0 = *(const float2*)(pr2 + kb),     c1 = *(const float2*)(pr3 + kb);
        float2 c2 = *(const float2*)(pr2 + kb + 8), c3 = *(const float2*)(pr3 + kb + 8);
        uint4 h1v = make_uint4(h2u2(a0.x, a0.y), h2u2(a1.x, a1.y), h2u2(a2.x, a2.y), h2u2(a3.x, a3.y));
        uint4 h2v = make_uint4(h2u2(c0.x, c0.y), h2u2(c1.x, c1.y), h2u2(c2.x, c2.y), h2u2(c3.x, c3.y));
        *(uint4*)(As + gc_ * 528 + (grg * 4 + gtig) * 16)       = h1v;
        *(uint4*)(As + gc_ * 528 + ((grg + 4) * 4 + gtig) * 16) = h2v;
    }
    __syncthreads();

    for (int gcc = 0; gcc < 12; ++gcc) {
        const int slot = gcc & 1;
        const bool doGather = (gcc + 1 < 12);

        float2 a0, a1, a2, a3, c0, c1, c2, c3;
        if (doGather) {
            int gn = gcc + 1;
            int seg = gn >> 2;
            int kb = (gn & 3) * 64 + gs * 16 + gtig * 2;
            const float* pr0 = rowptr[seg * 64 + gr0];
            const float* pr1 = rowptr[seg * 64 + gr0 + 8];
            const float* pr2 = rowptr[seg * 64 + gr0 + 4];
            const float* pr3 = rowptr[seg * 64 + gr0 + 12];
            a0 = *(const float2*)(pr0 + kb);     a1 = *(const float2*)(pr1 + kb);
            a2 = *(const float2*)(pr0 + kb + 8); a3 = *(const float2*)(pr1 + kb + 8);
            c0 = *(const float2*)(pr2 + kb);     c1 = *(const float2*)(pr3 + kb);
            c2 = *(const float2*)(pr2 + kb + 8); c3 = *(const float2*)(pr3 + kb + 8);
        }

        const char* ab = As + slot * ASLOT;
        const uint2* wp = g_W + ((size_t)(gcc * 4) * 32 + jt) * 32 + lane;
        uint2 B = wp[0];
        #pragma unroll
        for (int ks = 0; ks < 4; ++ks) {
            uint2 Bn;
            if (ks < 3) Bn = wp[(ks + 1) * 1024];
            #pragma unroll
            for (int i = 0; i < 4; ++i) {
                uint4 A0 = *(const uint4*)(ab + (i * 4 + ks) * 528 + lane * 16);
                mma16816(acc[i], A0.x, A0.y, A0.z, A0.w, B.x, B.y);
            }
            if (ks < 3) B = Bn;
        }

        if (doGather) {
            uint4 h1v = make_uint4(h2u2(a0.x, a0.y), h2u2(a1.x, a1.y), h2u2(a2.x, a2.y), h2u2(a3.x, a3.y));
            uint4 h2v = make_uint4(h2u2(c0.x, c0.y), h2u2(c1.x, c1.y), h2u2(c2.x, c2.y), h2u2(c3.x, c3.y));
            char* sb = As + (slot ^ 1) * ASLOT + gc_ * 528;
            *(uint4*)(sb + (grg * 4 + gtig) * 16)       = h1v;
            *(uint4*)(sb + ((grg + 4) * 4 + gtig) * 16) = h2v;
        }
        __syncthreads();
    }

    {
        int cb = cs4 * 64 + wn * 8 + tig * 2;
        float b0v = b_in[cb], b1v = b_in[cb + 1];
        int sg = cs4 * 4 + (wn >> 1);
        int hoff = (wn & 1) * 8;
        #pragma unroll
        for (int i = 0; i < 4; ++i) {
            float v0 = elu1(acc[i][0] + b0v);
            float v1 = elu1(acc[i][1] + b1v);
            float v2 = elu1(acc[i][2] + b0v);
            float v3 = elu1(acc[i][3] + b1v);
            char* dst = (char*)(g_actA + (size_t)nloc * 2048 + (i * 16 + sg) * 32 + lane) + hoff;
            *(uint2*)dst = make_uint2(h2u2(v0, v1), h2u2(v2, v3));
        }
    }
}

__global__ void __launch_bounds__(256, 2)
tail_l23(const int* __restrict__ tokens, const float* __restrict__ E,
         const float* __restrict__ bp, float* __restrict__ d_out, int level, int phase)
{
    extern __shared__ char smem[];
    const float** rowptr = (const float**)(smem + T2_RPTR);
    const uint32_t sb = smem_u32(smem);

    const int tid  = threadIdx.x;
    const int wn   = tid >> 5;
    const int lane = tid & 31;
    const int g    = lane >> 2;
    const int tig  = tid & 3;
    const int nloc = blockIdx.x >> 2;
    const int cs4  = blockIdx.x & 3;
    const int node = level - 1 + nloc;
    const int jt   = cs4 * 8 + wn;
    const int gbase = phase ? 16 : 12;
    const uint4* actSrc = (phase ? g_actB : g_actA) + (size_t)nloc * 2048;

    if (phase && tid < 64)
        rowptr[tid] = E + (size_t)tokens[tid * NTOK + node] * D;

    float acc[4][4];
    #pragma unroll
    for (int i = 0; i < 4; ++i)
        #pragma unroll
        for (int q = 0; q < 4; ++q) acc[i][q] = 0.f;

    // preload chunk 0: 512 uint4
    #pragma unroll
    for (int rr = 0; rr < 2; ++rr) {
        int idx = rr * 256 + tid;
        int i = idx >> 7, sgo = (idx >> 5) & 3, ln = idx & 31;
        cp_async16(sb + idx * 16, (const void*)(actSrc + (i * 16 + sgo) * 32 + ln));
    }
    cp_commit();

    #pragma unroll 1
    for (int c = 0; c < 4; ++c) {
        if (c + 1 < 4) {
            uint32_t dstb = sb + ((c + 1) & 1) * 8192;
            #pragma unroll
            for (int rr = 0; rr < 2; ++rr) {
                int idx = rr * 256 + tid;
                int i = idx >> 7, sgo = (idx >> 5) & 3, ln = idx & 31;
                cp_async16(dstb + idx * 16,
                           (const void*)(actSrc + (i * 16 + (c + 1) * 4 + sgo) * 32 + ln));
            }
            cp_commit();
            cp_wait<1>();
        } else {
            cp_wait<0>();
        }
        __syncthreads();

        const uint4* slot = (const uint4*)(smem + (c & 1) * 8192);
        const uint2* wp = g_W + ((size_t)((gbase + c) * 4) * 32 + jt) * 32 + lane;
        uint2 B = wp[0];
        #pragma unroll
        for (int ks = 0; ks < 4; ++ks) {
            uint2 Bn;
            if (ks < 3) Bn = wp[(ks + 1) * 1024];
            #pragma unroll
            for (int i = 0; i < 4; ++i) {
                uint4 A0 = slot[i * 128 + ks * 32 + lane];
                mma16816(acc[i], A0.x, A0.y, A0.z, A0.w, B.x, B.y);
            }
            if (ks < 3) B = Bn;
        }
        __syncthreads();
    }

    int cb = cs4 * 64 + wn * 8 + tig * 2;
    float b0v = bp[cb], b1v = bp[cb + 1];
    if (phase == 0) {
        int sg = cs4 * 4 + (wn >> 1);
        int hoff = (wn & 1) * 8;
        #pragma unroll
        for (int i = 0; i < 4; ++i) {
            float v0 = elu1(acc[i][0] + b0v);
            float v1 = elu1(acc[i][1] + b1v);
            float v2 = elu1(acc[i][2] + b0v);
            float v3 = elu1(acc[i][3] + b1v);
            char* dst = (char*)(g_actB + (size_t)nloc * 2048 + (i * 16 + sg) * 32 + lane) + hoff;
            *(uint2*)dst = make_uint2(h2u2(v0, v1), h2u2(v2, v3));
        }
    } else {
        #pragma unroll
        for (int i = 0; i < 4; ++i) {
            int r0 = i * 16 + g, r1 = r0 + 8;
            float2 e0 = *(const float2*)(rowptr[r0] + cb);
            float2 e1 = *(const float2*)(rowptr[r1] + cb);
            float2 o0 = make_float2(acc[i][0] + b0v + e0.x, acc[i][1] + b1v + e0.y);
            float2 o1 = make_float2(acc[i][2] + b0v + e1.x, acc[i][3] + b1v + e1.y);
            if (level == 1) {
                *(float2*)(d_out + (size_t)r0 * D + cb) = o0;
                *(float2*)(d_out + (size_t)r1 * D + cb) = o1;
            } else {
                *(float2*)(g_node_val + ((size_t)node * BATCH + r0) * D + cb) = o0;
                *(float2*)(g_node_val + ((size_t)node * BATCH + r1) * D + cb) = o1;
            }
        }
    }
}

extern "C" void kernel_launch(void* const* d_in, const int* in_sizes, int n_in,
                              void* d_out, int out_size) {
    const int*   tokens = (const int*)d_in[0];
    const float* E      = (const float*)d_in[1];
    const float* W_in   = (const float*)d_in[2];
    const float* b_in   = (const float*)d_in[3];
    const float* W1     = (const float*)d_in[4];
    const float* b1     = (const float*)d_in[5];
    const float* W2     = (const float*)d_in[6];
    const float* b2     = (const float*)d_in[7];
    float* out = (float*)d_out;

    cudaFuncSetAttribute(level_kernel, cudaFuncAttributeMaxDynamicSharedMemorySize, SMEM_TOTAL);
    cudaFuncSetAttribute(tail_l1,  cudaFuncAttributeMaxDynamicSharedMemorySize, T1_SMEM);
    cudaFuncSetAttribute(tail_l23, cudaFuncAttributeMaxDynamicSharedMemorySize, T2_SMEM);

    prep_weights<<<(NCH * 4096) / 256, 256>>>(W_in, W1, W2);

    for (int level = 1024; level >= 256; level >>= 1)
        level_kernel<<<level, 256, SMEM_TOTAL>>>(tokens, E, b_in, b1, b2, out, level);

    for (int level = 128; level >= 1; level >>= 1) {
        tail_l1 <<<level * 4, 256, T1_SMEM>>>(tokens, E, b_in, level);
        tail_l23<<<level * 4, 256, T2_SMEM>>>(tokens, E, b1, out, level, 0);
        tail_l23<<<level * 4, 256, T2_SMEM>>>(tokens, E, b2, out, level, 1);
    }
}

// round 16
// speedup vs baseline: 2.0230x; 1.1123x over previous
#include <cuda_runtime.h>
#include <cuda_fp16.h>
#include <cstdint>

#define BATCH 64
#define D 256
#define NTOK 4095
#define NCH 20             // 12 (layer1 K=768) + 4 (layer2) + 4 (layer3), K-chunk = 64

__device__ __align__(256) uint2 g_W[NCH * 4096];   // fp16 {pair0, pair1}, frag-major, 640 KB
// inter-level node activations: fp16 frag-major, residual included: [node][ (i*16+sg)*32+lane ]
__device__ __align__(256) uint4 g_nodeH[2047 * 2048];
// intra-tail layer ping-pong (fp16 frag-major, per nloc)
__device__ __align__(256) uint4 g_actA[128 * 2048];
__device__ __align__(256) uint4 g_actB[128 * 2048];

// ---------------- SMEM layout ----------------
// fused kernel: As ring 2x8448 aliases Af [0,32768); bias @32768; rowptr @35840
#define ASLOT   8448
#define BIASOFF 32768
#define RPTROFF 35840
#define SMEM_TOTAL 37376
// tail L1: As ring [0,16896) + rowptr @16896 (64 ptrs)
#define T1_RPTR   16896
#define T1_SMEM   17408
// tail L2/3: stage 2 x 8KB + rowptr @16384 (64 ptrs)
#define T2_RPTR   16384
#define T2_SMEM   16896

// ---------------- helpers ----------------
__device__ __forceinline__ uint32_t smem_u32(const void* p) {
    uint32_t a;
    asm("{ .reg .u64 t; cvta.to.shared.u64 t, %1; cvt.u32.u64 %0, t; }" : "=r"(a) : "l"(p));
    return a;
}
__device__ __forceinline__ void cp_async16(uint32_t dst, const void* src) {
    asm volatile("cp.async.cg.shared.global [%0], [%1], 16;" :: "r"(dst), "l"(src) : "memory");
}
__device__ __forceinline__ void cp_commit() { asm volatile("cp.async.commit_group;" ::: "memory"); }
template<int N> __device__ __forceinline__ void cp_wait() {
    asm volatile("cp.async.wait_group %0;" :: "n"(N) : "memory");
}
__device__ __forceinline__ void mma16816(float d[4], uint32_t a0, uint32_t a1, uint32_t a2, uint32_t a3,
                                         uint32_t b0, uint32_t b1) {
    asm volatile("mma.sync.aligned.m16n8k16.row.col.f32.f16.f16.f32 "
                 "{%0,%1,%2,%3}, {%4,%5,%6,%7}, {%8,%9}, {%0,%1,%2,%3};"
                 : "+f"(d[0]), "+f"(d[1]), "+f"(d[2]), "+f"(d[3])
                 : "r"(a0), "r"(a1), "r"(a2), "r"(a3), "r"(b0), "r"(b1));
}
__device__ __forceinline__ uint32_t h2u2(float x, float y) {
    __half2 h = __floats2half2_rn(x, y);
    return *reinterpret_cast<uint32_t*>(&h);
}
__device__ __forceinline__ float elu1(float v) { return v > 0.f ? v : (__expf(v) - 1.f); }

// -------- weight prep: fp32 -> fp16, frag-major K64 chunks --------
__global__ void prep_weights(const float* __restrict__ W_in,
                             const float* __restrict__ W1,
                             const float* __restrict__ W2) {
    int idx = blockIdx.x * 256 + threadIdx.x;
    if (idx >= NCH * 4096) return;
    int lane = idx & 31;
    int jt   = (idx >> 5) & 31;
    int s    = (idx >> 10) & 3;
    int gcw  = idx >> 12;
    int n  = jt * 8 + (lane >> 2);
    int tg = lane & 3;
    const float* Wsrc; int K, kb;
    if (gcw < 12)      { Wsrc = W_in; K = 768; kb = gcw * 64; }
    else if (gcw < 16) { Wsrc = W1;   K = 256; kb = (gcw - 12) * 64; }
    else               { Wsrc = W2;   K = 256; kb = (gcw - 16) * 64; }
    int k0 = kb + s * 16 + tg * 2;
    g_W[idx] = make_uint2(h2u2(Wsrc[n * K + k0],     Wsrc[n * K + k0 + 1]),
                          h2u2(Wsrc[n * K + k0 + 8], Wsrc[n * K + k0 + 9]));
}

__device__ __forceinline__ void ldgB(uint2 B[4], int gc, int ks, int wn, int lane) {
    const uint2* wp = g_W + (((gc * 4 + ks) * 32) + wn * 4) * 32 + lane;
    B[0] = wp[0];
    B[1] = wp[32];
    B[2] = wp[64];
    B[3] = wp[96];
}

// ================= fused 3-layer kernel (levels >= 256) =================
__global__ void __launch_bounds__(256, 2)
level_kernel(const int* __restrict__ tokens, const float* __restrict__ E,
             const float* __restrict__ b_in, const float* __restrict__ b1,
             const float* __restrict__ b2, int level)
{
    extern __shared__ char smem[];
    float* bias = (float*)(smem + BIASOFF);
    const float** rowptr = (const float**)(smem + RPTROFF);
    char* As = smem;
    char* Af = smem;
    const uint32_t sbA = smem_u32(smem);

    const int tid  = threadIdx.x;
    const int wn   = tid >> 5;
    const int lane = tid & 31;
    const int g    = lane >> 2;
    const int tig  = lane & 3;
    const int node = level - 1 + blockIdx.x;
    const bool leaf = (level == 1024);

    const int gc_  = tid >> 4;
    const int grg  = (tid >> 2) & 3;
    const int gtig = tid & 3;
    const int gr0  = (gc_ >> 2) * 16 + grg;
    const int gs   = gc_ & 3;

    bias[tid]       = b_in[tid];
    bias[256 + tid] = b1[tid];
    bias[512 + tid] = b2[tid];
    if (tid < 64) {
        int b = tid;
        rowptr[tid] = E + (size_t)tokens[b * NTOK + node] * D;
        if (leaf) {
            rowptr[64 + tid]  = E + (size_t)tokens[b * NTOK + 2 * node + 1] * D;
            rowptr[128 + tid] = E + (size_t)tokens[b * NTOK + 2 * node + 2] * D;
        }
    }

    float acc[4][4][4];
    #pragma unroll
    for (int i = 0; i < 4; ++i)
        #pragma unroll
        for (int j = 0; j < 4; ++j)
            #pragma unroll
            for (int q = 0; q < 4; ++q) acc[i][j][q] = 0.f;

    __syncthreads();

    {   // A(0) gather (roots from E, fp16)
        const float* pr0 = rowptr[gr0];
        const float* pr1 = rowptr[gr0 + 8];
        const float* pr2 = rowptr[gr0 + 4];
        const float* pr3 = rowptr[gr0 + 12];
        int kb = gs * 16 + gtig * 2;
        float2 a0 = *(const float2*)(pr0 + kb),     a1 = *(const float2*)(pr1 + kb);
        float2 a2 = *(const float2*)(pr0 + kb + 8), a3 = *(const float2*)(pr1 + kb + 8);
        float2 c0 = *(const float2*)(pr2 + kb),     c1 = *(const float2*)(pr3 + kb);
        float2 c2 = *(const float2*)(pr2 + kb + 8), c3 = *(const float2*)(pr3 + kb + 8);
        uint4 h1v = make_uint4(h2u2(a0.x, a0.y), h2u2(a1.x, a1.y), h2u2(a2.x, a2.y), h2u2(a3.x, a3.y));
        uint4 h2v = make_uint4(h2u2(c0.x, c0.y), h2u2(c1.x, c1.y), h2u2(c2.x, c2.y), h2u2(c3.x, c3.y));
        *(uint4*)(As + gc_ * 528 + (grg * 4 + gtig) * 16)       = h1v;
        *(uint4*)(As + gc_ * 528 + ((grg + 4) * 4 + gtig) * 16) = h2v;
    }
    __syncthreads();

    for (int gcc = 0; gcc < 12; ++gcc) {
        const int slot = gcc & 1;
        const int gn = gcc + 1;
        const bool pfGather = (gn < 12) && (leaf || gn < 4);
        const bool pfCp     = (gn < 12) && !leaf && (gn >= 4);

        float2 a0, a1, a2, a3, c0, c1, c2, c3;
        if (pfGather) {
            int seg = gn >> 2;
            int kb = (gn & 3) * 64 + gs * 16 + gtig * 2;
            const float* pr0 = rowptr[seg * 64 + gr0];
            const float* pr1 = rowptr[seg * 64 + gr0 + 8];
            const float* pr2 = rowptr[seg * 64 + gr0 + 4];
            const float* pr3 = rowptr[seg * 64 + gr0 + 12];
            a0 = *(const float2*)(pr0 + kb);     a1 = *(const float2*)(pr1 + kb);
            a2 = *(const float2*)(pr0 + kb + 8); a3 = *(const float2*)(pr1 + kb + 8);
            c0 = *(const float2*)(pr2 + kb);     c1 = *(const float2*)(pr3 + kb);
            c2 = *(const float2*)(pr2 + kb + 8); c3 = *(const float2*)(pr3 + kb + 8);
        } else if (pfCp) {
            const uint4* src = g_nodeH + (size_t)(2 * node + 1 + (gn >= 8 ? 1 : 0)) * 2048;
            int sg0 = ((gn - 4) & 3) * 4;
            uint32_t dstb = sbA + (gn & 1) * ASLOT;
            #pragma unroll
            for (int rr = 0; rr < 2; ++rr) {
                int idx = rr * 256 + tid;
                int i = idx >> 7, ks = (idx >> 5) & 3, ln = idx & 31;
                cp_async16(dstb + (i * 4 + ks) * 528 + ln * 16,
                           (const void*)(src + (i * 16 + sg0 + ks) * 32 + ln));
            }
            cp_commit();
        }

        const char* ab = As + slot * ASLOT;
        uint2 B[4];
        ldgB(B, gcc, 0, wn, lane);
        #pragma unroll
        for (int ks = 0; ks < 4; ++ks) {
            uint2 Bn[4];
            if (ks < 3) ldgB(Bn, gcc, ks + 1, wn, lane);
            #pragma unroll
            for (int half = 0; half < 2; ++half) {
                uint4 A0 = *(const uint4*)(ab + ((half * 2 + 0) * 4 + ks) * 528 + lane * 16);
                uint4 A1 = *(const uint4*)(ab + ((half * 2 + 1) * 4 + ks) * 528 + lane * 16);
                #pragma unroll
                for (int j = 0; j < 4; ++j) {
                    mma16816(acc[half * 2 + 0][j], A0.x, A0.y, A0.z, A0.w, B[j].x, B[j].y);
                    mma16816(acc[half * 2 + 1][j], A1.x, A1.y, A1.z, A1.w, B[j].x, B[j].y);
                }
            }
            if (ks < 3) { B[0] = Bn[0]; B[1] = Bn[1]; B[2] = Bn[2]; B[3] = Bn[3]; }
        }

        if (pfGather) {
            uint4 h1v = make_uint4(h2u2(a0.x, a0.y), h2u2(a1.x, a1.y), h2u2(a2.x, a2.y), h2u2(a3.x, a3.y));
            uint4 h2v = make_uint4(h2u2(c0.x, c0.y), h2u2(c1.x, c1.y), h2u2(c2.x, c2.y), h2u2(c3.x, c3.y));
            char* sb = As + (slot ^ 1) * ASLOT + gc_ * 528;
            *(uint4*)(sb + (grg * 4 + gtig) * 16)       = h1v;
            *(uint4*)(sb + ((grg + 4) * 4 + gtig) * 16) = h2v;
        }
        if (pfCp) cp_wait<0>();
        __syncthreads();
    }

    // mid epilogue 1: bias + ELU -> Af (fp16)
    #pragma unroll
    for (int i = 0; i < 4; ++i) {
        #pragma unroll
        for (int jp = 0; jp < 2; ++jp) {
            uint4 hv;
            #pragma unroll
            for (int u = 0; u < 2; ++u) {
                int j = 2 * jp + u;
                int cb = wn * 32 + j * 8 + tig * 2;
                float v0 = elu1(acc[i][j][0] + bias[cb]);
                float v1 = elu1(acc[i][j][1] + bias[cb + 1]);
                float v2 = elu1(acc[i][j][2] + bias[cb]);
                float v3 = elu1(acc[i][j][3] + bias[cb + 1]);
                if (u == 0) { hv.x = h2u2(v0, v1); hv.y = h2u2(v2, v3); }
                else        { hv.z = h2u2(v0, v1); hv.w = h2u2(v2, v3); }
                acc[i][j][0] = acc[i][j][1] = acc[i][j][2] = acc[i][j][3] = 0.f;
            }
            *(uint4*)(Af + ((i * 16 + wn * 2 + jp) * 32 + lane) * 16) = hv;
        }
    }
    __syncthreads();

    // layers 2 & 3
    #pragma unroll 1
    for (int layer = 1; layer <= 2; ++layer) {
        const int gbase = (layer == 1) ? 12 : 16;
        #pragma unroll 1
        for (int c = 0; c < 4; ++c) {
            const int gcw = gbase + c;
            uint2 B[4];
            ldgB(B, gcw, 0, wn, lane);
            #pragma unroll
            for (int ks = 0; ks < 4; ++ks) {
                uint2 Bn[4];
                if (ks < 3) ldgB(Bn, gcw, ks + 1, wn, lane);
                int sg = c * 4 + ks;
                #pragma unroll
                for (int half = 0; half < 2; ++half) {
                    uint4 A0 = *(const uint4*)(Af + (((half * 2 + 0) * 16 + sg) * 32 + lane) * 16);
                    uint4 A1 = *(const uint4*)(Af + (((half * 2 + 1) * 16 + sg) * 32 + lane) * 16);
                    #pragma unroll
                    for (int j = 0; j < 4; ++j) {
                        mma16816(acc[half * 2 + 0][j], A0.x, A0.y, A0.z, A0.w, B[j].x, B[j].y);
                        mma16816(acc[half * 2 + 1][j], A1.x, A1.y, A1.z, A1.w, B[j].x, B[j].y);
                    }
                }
                if (ks < 3) { B[0] = Bn[0]; B[1] = Bn[1]; B[2] = Bn[2]; B[3] = Bn[3]; }
            }
        }

        if (layer == 1) {
            __syncthreads();
            #pragma unroll
            for (int i = 0; i < 4; ++i) {
                #pragma unroll
                for (int jp = 0; jp < 2; ++jp) {
                    uint4 hv;
                    #pragma unroll
                    for (int u = 0; u < 2; ++u) {
                        int j = 2 * jp + u;
                        int cb = wn * 32 + j * 8 + tig * 2;
                        float v0 = elu1(acc[i][j][0] + bias[256 + cb]);
                        float v1 = elu1(acc[i][j][1] + bias[256 + cb + 1]);
                        float v2 = elu1(acc[i][j][2] + bias[256 + cb]);
                        float v3 = elu1(acc[i][j][3] + bias[256 + cb + 1]);
                        if (u == 0) { hv.x = h2u2(v0, v1); hv.y = h2u2(v2, v3); }
                        else        { hv.z = h2u2(v0, v1); hv.w = h2u2(v2, v3); }
                        acc[i][j][0] = acc[i][j][1] = acc[i][j][2] = acc[i][j][3] = 0.f;
                    }
                    *(uint4*)(Af + ((i * 16 + wn * 2 + jp) * 32 + lane) * 16) = hv;
                }
            }
            __syncthreads();
        }
    }

    // final epilogue: acc + b2 + E residual -> g_nodeH[node] (fp16 frag-major)
    #pragma unroll
    for (int i = 0; i < 4; ++i) {
        int r_g  = i * 16 + g;
        int r_g8 = r_g + 8;
        const float* e0p = rowptr[r_g];
        const float* e1p = rowptr[r_g8];
        #pragma unroll
        for (int j = 0; j < 4; ++j) {
            int cb = wn * 32 + j * 8 + tig * 2;
            float b0v = bias[512 + cb], b1v = bias[512 + cb + 1];
            float2 e0 = *(const float2*)(e0p + cb);
            float2 e1 = *(const float2*)(e1p + cb);
            float o0 = acc[i][j][0] + b0v + e0.x, o1 = acc[i][j][1] + b1v + e0.y;
            float o2 = acc[i][j][2] + b0v + e1.x, o3 = acc[i][j][3] + b1v + e1.y;
            int sg = wn * 2 + (j >> 1);
            int hoff = (j & 1) * 8;
            char* dst = (char*)(g_nodeH + (size_t)node * 2048 + (i * 16 + sg) * 32 + lane) + hoff;
            *(uint2*)dst = make_uint2(h2u2(o0, o1), h2u2(o2, o3));
        }
    }
}

// ================= tail path (levels <= 128): per-layer, N split 4-ways =================

__global__ void __launch_bounds__(256, 2)
tail_l1(const int* __restrict__ tokens, const float* __restrict__ E,
        const float* __restrict__ b_in, int level)
{
    extern __shared__ char smem[];
    const float** rowptr = (const float**)(smem + T1_RPTR);
    char* As = smem;
    const uint32_t sbA = smem_u32(smem);

    const int tid  = threadIdx.x;
    const int wn   = tid >> 5;
    const int lane = tid & 31;
    const int tig  = lane & 3;
    const int nloc = blockIdx.x >> 2;
    const int cs4  = blockIdx.x & 3;
    const int node = level - 1 + nloc;
    const int jt   = cs4 * 8 + wn;

    const int gc_  = tid >> 4;
    const int grg  = (tid >> 2) & 3;
    const int gtig = tid & 3;
    const int gr0  = (gc_ >> 2) * 16 + grg;
    const int gs   = gc_ & 3;

    if (tid < 64)
        rowptr[tid] = E + (size_t)tokens[tid * NTOK + node] * D;

    float acc[4][4];
    #pragma unroll
    for (int i = 0; i < 4; ++i)
        #pragma unroll
        for (int q = 0; q < 4; ++q) acc[i][q] = 0.f;

    __syncthreads();
    {   // A(0) roots from E
        const float* pr0 = rowptr[gr0];
        const float* pr1 = rowptr[gr0 + 8];
        const float* pr2 = rowptr[gr0 + 4];
        const float* pr3 = rowptr[gr0 + 12];
        int kb = gs * 16 + gtig * 2;
        float2 a0 = *(const float2*)(pr0 + kb),     a1 = *(const float2*)(pr1 + kb);
        float2 a2 = *(const float2*)(pr0 + kb + 8), a3 = *(const float2*)(pr1 + kb + 8);
        float2 c0 = *(const float2*)(pr2 + kb),     c1 = *(const float2*)(pr3 + kb);
        float2 c2 = *(const float2*)(pr2 + kb + 8), c3 = *(const float2*)(pr3 + kb + 8);
        uint4 h1v = make_uint4(h2u2(a0.x, a0.y), h2u2(a1.x, a1.y), h2u2(a2.x, a2.y), h2u2(a3.x, a3.y));
        uint4 h2v = make_uint4(h2u2(c0.x, c0.y), h2u2(c1.x, c1.y), h2u2(c2.x, c2.y), h2u2(c3.x, c3.y));
        *(uint4*)(As + gc_ * 528 + (grg * 4 + gtig) * 16)       = h1v;
        *(uint4*)(As + gc_ * 528 + ((grg + 4) * 4 + gtig) * 16) = h2v;
    }
    __syncthreads();

    for (int gcc = 0; gcc < 12; ++gcc) {
        const int slot = gcc & 1;
        const int gn = gcc + 1;
        const bool pfGather = (gn < 4);
        const bool pfCp     = (gn >= 4 && gn < 12);

        float2 a0, a1, a2, a3, c0, c1, c2, c3;
        if (pfGather) {
            int kb = (gn & 3) * 64 + gs * 16 + gtig * 2;
            const float* pr0 = rowptr[gr0];
            const float* pr1 = rowptr[gr0 + 8];
            const float* pr2 = rowptr[gr0 + 4];
            const float* pr3 = rowptr[gr0 + 12];
            a0 = *(const float2*)(pr0 + kb);     a1 = *(const float2*)(pr1 + kb);
            a2 = *(const float2*)(pr0 + kb + 8); a3 = *(const float2*)(pr1 + kb + 8);
            c0 = *(const float2*)(pr2 + kb);     c1 = *(const float2*)(pr3 + kb);
            c2 = *(const float2*)(pr2 + kb + 8); c3 = *(const float2*)(pr3 + kb + 8);
        } else if (pfCp) {
            const uint4* src = g_nodeH + (size_t)(2 * node + 1 + (gn >= 8 ? 1 : 0)) * 2048;
            int sg0 = ((gn - 4) & 3) * 4;
            uint32_t dstb = sbA + (gn & 1) * ASLOT;
            #pragma unroll
            for (int rr = 0; rr < 2; ++rr) {
                int idx = rr * 256 + tid;
                int i = idx >> 7, ks = (idx >> 5) & 3, ln = idx & 31;
                cp_async16(dstb + (i * 4 + ks) * 528 + ln * 16,
                           (const void*)(src + (i * 16 + sg0 + ks) * 32 + ln));
            }
            cp_commit();
        }

        const char* ab = As + slot * ASLOT;
        const uint2* wp = g_W + ((size_t)(gcc * 4) * 32 + jt) * 32 + lane;
        uint2 B = wp[0];
        #pragma unroll
        for (int ks = 0; ks < 4; ++ks) {
            uint2 Bn;
            if (ks < 3) Bn = wp[(ks + 1) * 1024];
            #pragma unroll
            for (int i = 0; i < 4; ++i) {
                uint4 A0 = *(const uint4*)(ab + (i * 4 + ks) * 528 + lane * 16);
                mma16816(acc[i], A0.x, A0.y, A0.z, A0.w, B.x, B.y);
            }
            if (ks < 3) B = Bn;
        }

        if (pfGather) {
            uint4 h1v = make_uint4(h2u2(a0.x, a0.y), h2u2(a1.x, a1.y), h2u2(a2.x, a2.y), h2u2(a3.x, a3.y));
            uint4 h2v = make_uint4(h2u2(c0.x, c0.y), h2u2(c1.x, c1.y), h2u2(c2.x, c2.y), h2u2(c3.x, c3.y));
            char* sb = As + (slot ^ 1) * ASLOT + gc_ * 528;
            *(uint4*)(sb + (grg * 4 + gtig) * 16)       = h1v;
            *(uint4*)(sb + ((grg + 4) * 4 + gtig) * 16) = h2v;
        }
        if (pfCp) cp_wait<0>();
        __syncthreads();
    }

    {
        int cb = cs4 * 64 + wn * 8 + tig * 2;
        float b0v = b_in[cb], b1v = b_in[cb + 1];
        int sg = cs4 * 4 + (wn >> 1);
        int hoff = (wn & 1) * 8;
        #pragma unroll
        for (int i = 0; i < 4; ++i) {
            float v0 = elu1(acc[i][0] + b0v);
            float v1 = elu1(acc[i][1] + b1v);
            float v2 = elu1(acc[i][2] + b0v);
            float v3 = elu1(acc[i][3] + b1v);
            char* dst = (char*)(g_actA + (size_t)nloc * 2048 + (i * 16 + sg) * 32 + lane) + hoff;
            *(uint2*)dst = make_uint2(h2u2(v0, v1), h2u2(v2, v3));
        }
    }
}

__global__ void __launch_bounds__(256, 2)
tail_l23(const int* __restrict__ tokens, const float* __restrict__ E,
         const float* __restrict__ bp, float* __restrict__ d_out, int level, int phase)
{
    extern __shared__ char smem[];
    const float** rowptr = (const float**)(smem + T2_RPTR);
    const uint32_t sb = smem_u32(smem);

    const int tid  = threadIdx.x;
    const int wn   = tid >> 5;
    const int lane = tid & 31;
    const int g    = lane >> 2;
    const int tig  = tid & 3;
    const int nloc = blockIdx.x >> 2;
    const int cs4  = blockIdx.x & 3;
    const int node = level - 1 + nloc;
    const int jt   = cs4 * 8 + wn;
    const int gbase = phase ? 16 : 12;
    const uint4* actSrc = (phase ? g_actB : g_actA) + (size_t)nloc * 2048;

    if (phase && tid < 64)
        rowptr[tid] = E + (size_t)tokens[tid * NTOK + node] * D;

    float acc[4][4];
    #pragma unroll
    for (int i = 0; i < 4; ++i)
        #pragma unroll
        for (int q = 0; q < 4; ++q) acc[i][q] = 0.f;

    // preload chunk 0: 512 uint4
    #pragma unroll
    for (int rr = 0; rr < 2; ++rr) {
        int idx = rr * 256 + tid;
        int i = idx >> 7, sgo = (idx >> 5) & 3, ln = idx & 31;
        cp_async16(sb + idx * 16, (const void*)(actSrc + (i * 16 + sgo) * 32 + ln));
    }
    cp_commit();

    #pragma unroll 1
    for (int c = 0; c < 4; ++c) {
        if (c + 1 < 4) {
            uint32_t dstb = sb + ((c + 1) & 1) * 8192;
            #pragma unroll
            for (int rr = 0; rr < 2; ++rr) {
                int idx = rr * 256 + tid;
                int i = idx >> 7, sgo = (idx >> 5) & 3, ln = idx & 31;
                cp_async16(dstb + idx * 16,
                           (const void*)(actSrc + (i * 16 + (c + 1) * 4 + sgo) * 32 + ln));
            }
            cp_commit();
            cp_wait<1>();
        } else {
            cp_wait<0>();
        }
        __syncthreads();

        const uint4* slot = (const uint4*)(smem + (c & 1) * 8192);
        const uint2* wp = g_W + ((size_t)((gbase + c) * 4) * 32 + jt) * 32 + lane;
        uint2 B = wp[0];
        #pragma unroll
        for (int ks = 0; ks < 4; ++ks) {
            uint2 Bn;
            if (ks < 3) Bn = wp[(ks + 1) * 1024];
            #pragma unroll
            for (int i = 0; i < 4; ++i) {
                uint4 A0 = slot[i * 128 + ks * 32 + lane];
                mma16816(acc[i], A0.x, A0.y, A0.z, A0.w, B.x, B.y);
            }
            if (ks < 3) B = Bn;
        }
        __syncthreads();
    }

    int cb = cs4 * 64 + wn * 8 + tig * 2;
    float b0v = bp[cb], b1v = bp[cb + 1];
    if (phase == 0) {
        int sg = cs4 * 4 + (wn >> 1);
        int hoff = (wn & 1) * 8;
        #pragma unroll
        for (int i = 0; i < 4; ++i) {
            float v0 = elu1(acc[i][0] + b0v);
            float v1 = elu1(acc[i][1] + b1v);
            float v2 = elu1(acc[i][2] + b0v);
            float v3 = elu1(acc[i][3] + b1v);
            char* dst = (char*)(g_actB + (size_t)nloc * 2048 + (i * 16 + sg) * 32 + lane) + hoff;
            *(uint2*)dst = make_uint2(h2u2(v0, v1), h2u2(v2, v3));
        }
    } else {
        int sg = cs4 * 4 + (wn >> 1);
        int hoff = (wn & 1) * 8;
        #pragma unroll
        for (int i = 0; i < 4; ++i) {
            int r0 = i * 16 + g, r1 = r0 + 8;
            float2 e0 = *(const float2*)(rowptr[r0] + cb);
            float2 e1 = *(const float2*)(rowptr[r1] + cb);
            float o0 = acc[i][0] + b0v + e0.x, o1 = acc[i][1] + b1v + e0.y;
            float o2 = acc[i][2] + b0v + e1.x, o3 = acc[i][3] + b1v + e1.y;
            if (level == 1) {
                *(float2*)(d_out + (size_t)r0 * D + cb) = make_float2(o0, o1);
                *(float2*)(d_out + (size_t)r1 * D + cb) = make_float2(o2, o3);
            } else {
                char* dst = (char*)(g_nodeH + (size_t)node * 2048 + (i * 16 + sg) * 32 + lane) + hoff;
                *(uint2*)dst = make_uint2(h2u2(o0, o1), h2u2(o2, o3));
            }
        }
    }
}

extern "C" void kernel_launch(void* const* d_in, const int* in_sizes, int n_in,
                              void* d_out, int out_size) {
    const int*   tokens = (const int*)d_in[0];
    const float* E      = (const float*)d_in[1];
    const float* W_in   = (const float*)d_in[2];
    const float* b_in   = (const float*)d_in[3];
    const float* W1     = (const float*)d_in[4];
    const float* b1     = (const float*)d_in[5];
    const float* W2     = (const float*)d_in[6];
    const float* b2     = (const float*)d_in[7];
    float* out = (float*)d_out;

    cudaFuncSetAttribute(level_kernel, cudaFuncAttributeMaxDynamicSharedMemorySize, SMEM_TOTAL);
    cudaFuncSetAttribute(tail_l1,  cudaFuncAttributeMaxDynamicSharedMemorySize, T1_SMEM);
    cudaFuncSetAttribute(tail_l23, cudaFuncAttributeMaxDynamicSharedMemorySize, T2_SMEM);

    prep_weights<<<(NCH * 4096) / 256, 256>>>(W_in, W1, W2);

    for (int level = 1024; level >= 256; level >>= 1)
        level_kernel<<<level, 256, SMEM_TOTAL>>>(tokens, E, b_in, b1, b2, level);

    for (int level = 128; level >= 1; level >>= 1) {
        tail_l1 <<<level * 4, 256, T1_SMEM>>>(tokens, E, b_in, level);
        tail_l23<<<level * 4, 256, T2_SMEM>>>(tokens, E, b1, out, level, 0);
        tail_l23<<<level * 4, 256, T2_SMEM>>>(tokens, E, b2, out, level, 1);
    }
}

// round 17
// speedup vs baseline: 2.4009x; 1.1868x over previous
#include <cuda_runtime.h>
#include <cuda_fp16.h>
#include <cstdint>

#define BATCH 64
#define D 256
#define NTOK 4095
#define NCH 20             // 12 (layer1 K=768) + 4 (layer2) + 4 (layer3), K-chunk = 64

__device__ __align__(256) uint2 g_W[NCH * 4096];        // fp16 {pair0,pair1}, frag-major (level_kernel)
__device__ __align__(256) uint2 g_W4[80 * 8 * 32 * 4];  // warp-packed: [ks][wn][lane][jj] (tail_fused)
// inter-level node activations: fp16 frag-major, residual included
__device__ __align__(256) uint4 g_nodeH[2047 * 2048];

// ---------------- SMEM layout ----------------
// fused kernel: As ring 2x8448 aliases Af [0,32768); bias @32768; rowptr @35840
#define ASLOT   8448
#define BIASOFF 32768
#define RPTROFF 35840
#define SMEM_TOTAL 37376
// tail_fused: A-l1 [0,24576) (roots 8K | child1 8K | child2 8K); Af @24576 (8K); bias @32768; rowptr @35840
#define TF_AF   24576
#define TF_BIAS 32768
#define TF_RPTR 35840
#define TF_SMEM 35968

// ---------------- helpers ----------------
__device__ __forceinline__ uint32_t smem_u32(const void* p) {
    uint32_t a;
    asm("{ .reg .u64 t; cvta.to.shared.u64 t, %1; cvt.u32.u64 %0, t; }" : "=r"(a) : "l"(p));
    return a;
}
__device__ __forceinline__ void cp_async16(uint32_t dst, const void* src) {
    asm volatile("cp.async.cg.shared.global [%0], [%1], 16;" :: "r"(dst), "l"(src) : "memory");
}
__device__ __forceinline__ void cp_commit() { asm volatile("cp.async.commit_group;" ::: "memory"); }
template<int N> __device__ __forceinline__ void cp_wait() {
    asm volatile("cp.async.wait_group %0;" :: "n"(N) : "memory");
}
__device__ __forceinline__ void mma16816(float d[4], uint32_t a0, uint32_t a1, uint32_t a2, uint32_t a3,
                                         uint32_t b0, uint32_t b1) {
    asm volatile("mma.sync.aligned.m16n8k16.row.col.f32.f16.f16.f32 "
                 "{%0,%1,%2,%3}, {%4,%5,%6,%7}, {%8,%9}, {%0,%1,%2,%3};"
                 : "+f"(d[0]), "+f"(d[1]), "+f"(d[2]), "+f"(d[3])
                 : "r"(a0), "r"(a1), "r"(a2), "r"(a3), "r"(b0), "r"(b1));
}
__device__ __forceinline__ uint32_t h2u2(float x, float y) {
    __half2 h = __floats2half2_rn(x, y);
    return *reinterpret_cast<uint32_t*>(&h);
}
__device__ __forceinline__ float elu1(float v) { return v > 0.f ? v : (__expf(v) - 1.f); }

// -------- weight prep: fp32 -> fp16, both fragment layouts --------
__global__ void prep_weights(const float* __restrict__ W_in,
                             const float* __restrict__ W1,
                             const float* __restrict__ W2) {
    int idx = blockIdx.x * 256 + threadIdx.x;
    if (idx >= NCH * 4096) return;
    int lane = idx & 31;
    int jt   = (idx >> 5) & 31;
    int s    = (idx >> 10) & 3;
    int gcw  = idx >> 12;
    int n  = jt * 8 + (lane >> 2);
    int tg = lane & 3;
    const float* Wsrc; int K, kb;
    if (gcw < 12)      { Wsrc = W_in; K = 768; kb = gcw * 64; }
    else if (gcw < 16) { Wsrc = W1;   K = 256; kb = (gcw - 12) * 64; }
    else               { Wsrc = W2;   K = 256; kb = (gcw - 16) * 64; }
    int k0 = kb + s * 16 + tg * 2;
    uint2 val = make_uint2(h2u2(Wsrc[n * K + k0],     Wsrc[n * K + k0 + 1]),
                           h2u2(Wsrc[n * K + k0 + 8], Wsrc[n * K + k0 + 9]));
    g_W[idx] = val;
    int ks = gcw * 4 + s;
    g_W4[(((ks * 8) + (jt >> 2)) * 32 + lane) * 4 + (jt & 3)] = val;
}

__device__ __forceinline__ void ldgB(uint2 B[4], int gc, int ks, int wn, int lane) {
    const uint2* wp = g_W + (((gc * 4 + ks) * 32) + wn * 4) * 32 + lane;
    B[0] = wp[0];
    B[1] = wp[32];
    B[2] = wp[64];
    B[3] = wp[96];
}

// ================= fused 3-layer kernel (levels >= 256) — R15-proven, unchanged =================
__global__ void __launch_bounds__(256, 2)
level_kernel(const int* __restrict__ tokens, const float* __restrict__ E,
             const float* __restrict__ b_in, const float* __restrict__ b1,
             const float* __restrict__ b2, int level)
{
    extern __shared__ char smem[];
    float* bias = (float*)(smem + BIASOFF);
    const float** rowptr = (const float**)(smem + RPTROFF);
    char* As = smem;
    char* Af = smem;
    const uint32_t sbA = smem_u32(smem);

    const int tid  = threadIdx.x;
    const int wn   = tid >> 5;
    const int lane = tid & 31;
    const int g    = lane >> 2;
    const int tig  = lane & 3;
    const int node = level - 1 + blockIdx.x;
    const bool leaf = (level == 1024);

    const int gc_  = tid >> 4;
    const int grg  = (tid >> 2) & 3;
    const int gtig = tid & 3;
    const int gr0  = (gc_ >> 2) * 16 + grg;
    const int gs   = gc_ & 3;

    bias[tid]       = b_in[tid];
    bias[256 + tid] = b1[tid];
    bias[512 + tid] = b2[tid];
    if (tid < 64) {
        int b = tid;
        rowptr[tid] = E + (size_t)tokens[b * NTOK + node] * D;
        if (leaf) {
            rowptr[64 + tid]  = E + (size_t)tokens[b * NTOK + 2 * node + 1] * D;
            rowptr[128 + tid] = E + (size_t)tokens[b * NTOK + 2 * node + 2] * D;
        }
    }

    float acc[4][4][4];
    #pragma unroll
    for (int i = 0; i < 4; ++i)
        #pragma unroll
        for (int j = 0; j < 4; ++j)
            #pragma unroll
            for (int q = 0; q < 4; ++q) acc[i][j][q] = 0.f;

    __syncthreads();

    {   // A(0) gather (roots from E, fp16)
        const float* pr0 = rowptr[gr0];
        const float* pr1 = rowptr[gr0 + 8];
        const float* pr2 = rowptr[gr0 + 4];
        const float* pr3 = rowptr[gr0 + 12];
        int kb = gs * 16 + gtig * 2;
        float2 a0 = *(const float2*)(pr0 + kb),     a1 = *(const float2*)(pr1 + kb);
        float2 a2 = *(const float2*)(pr0 + kb + 8), a3 = *(const float2*)(pr1 + kb + 8);
        float2 c0 = *(const float2*)(pr2 + kb),     c1 = *(const float2*)(pr3 + kb);
        float2 c2 = *(const float2*)(pr2 + kb + 8), c3 = *(const float2*)(pr3 + kb + 8);
        uint4 h1v = make_uint4(h2u2(a0.x, a0.y), h2u2(a1.x, a1.y), h2u2(a2.x, a2.y), h2u2(a3.x, a3.y));
        uint4 h2v = make_uint4(h2u2(c0.x, c0.y), h2u2(c1.x, c1.y), h2u2(c2.x, c2.y), h2u2(c3.x, c3.y));
        *(uint4*)(As + gc_ * 528 + (grg * 4 + gtig) * 16)       = h1v;
        *(uint4*)(As + gc_ * 528 + ((grg + 4) * 4 + gtig) * 16) = h2v;
    }
    __syncthreads();

    for (int gcc = 0; gcc < 12; ++gcc) {
        const int slot = gcc & 1;
        const int gn = gcc + 1;
        const bool pfGather = (gn < 12) && (leaf || gn < 4);
        const bool pfCp     = (gn < 12) && !leaf && (gn >= 4);

        float2 a0, a1, a2, a3, c0, c1, c2, c3;
        if (pfGather) {
            int seg = gn >> 2;
            int kb = (gn & 3) * 64 + gs * 16 + gtig * 2;
            const float* pr0 = rowptr[seg * 64 + gr0];
            const float* pr1 = rowptr[seg * 64 + gr0 + 8];
            const float* pr2 = rowptr[seg * 64 + gr0 + 4];
            const float* pr3 = rowptr[seg * 64 + gr0 + 12];
            a0 = *(const float2*)(pr0 + kb);     a1 = *(const float2*)(pr1 + kb);
            a2 = *(const float2*)(pr0 + kb + 8); a3 = *(const float2*)(pr1 + kb + 8);
            c0 = *(const float2*)(pr2 + kb);     c1 = *(const float2*)(pr3 + kb);
            c2 = *(const float2*)(pr2 + kb + 8); c3 = *(const float2*)(pr3 + kb + 8);
        } else if (pfCp) {
            const uint4* src = g_nodeH + (size_t)(2 * node + 1 + (gn >= 8 ? 1 : 0)) * 2048;
            int sg0 = ((gn - 4) & 3) * 4;
            uint32_t dstb = sbA + (gn & 1) * ASLOT;
            #pragma unroll
            for (int rr = 0; rr < 2; ++rr) {
                int idx = rr * 256 + tid;
                int i = idx >> 7, ks = (idx >> 5) & 3, ln = idx & 31;
                cp_async16(dstb + (i * 4 + ks) * 528 + ln * 16,
                           (const void*)(src + (i * 16 + sg0 + ks) * 32 + ln));
            }
            cp_commit();
        }

        const char* ab = As + slot * ASLOT;
        uint2 B[4];
        ldgB(B, gcc, 0, wn, lane);
        #pragma unroll
        for (int ks = 0; ks < 4; ++ks) {
            uint2 Bn[4];
            if (ks < 3) ldgB(Bn, gcc, ks + 1, wn, lane);
            #pragma unroll
            for (int half = 0; half < 2; ++half) {
                uint4 A0 = *(const uint4*)(ab + ((half * 2 + 0) * 4 + ks) * 528 + lane * 16);
                uint4 A1 = *(const uint4*)(ab + ((half * 2 + 1) * 4 + ks) * 528 + lane * 16);
                #pragma unroll
                for (int j = 0; j < 4; ++j) {
                    mma16816(acc[half * 2 + 0][j], A0.x, A0.y, A0.z, A0.w, B[j].x, B[j].y);
                    mma16816(acc[half * 2 + 1][j], A1.x, A1.y, A1.z, A1.w, B[j].x, B[j].y);
                }
            }
            if (ks < 3) { B[0] = Bn[0]; B[1] = Bn[1]; B[2] = Bn[2]; B[3] = Bn[3]; }
        }

        if (pfGather) {
            uint4 h1v = make_uint4(h2u2(a0.x, a0.y), h2u2(a1.x, a1.y), h2u2(a2.x, a2.y), h2u2(a3.x, a3.y));
            uint4 h2v = make_uint4(h2u2(c0.x, c0.y), h2u2(c1.x, c1.y), h2u2(c2.x, c2.y), h2u2(c3.x, c3.y));
            char* sb = As + (slot ^ 1) * ASLOT + gc_ * 528;
            *(uint4*)(sb + (grg * 4 + gtig) * 16)       = h1v;
            *(uint4*)(sb + ((grg + 4) * 4 + gtig) * 16) = h2v;
        }
        if (pfCp) cp_wait<0>();
        __syncthreads();
    }

    // mid epilogue 1: bias + ELU -> Af (fp16)
    #pragma unroll
    for (int i = 0; i < 4; ++i) {
        #pragma unroll
        for (int jp = 0; jp < 2; ++jp) {
            uint4 hv;
            #pragma unroll
            for (int u = 0; u < 2; ++u) {
                int j = 2 * jp + u;
                int cb = wn * 32 + j * 8 + tig * 2;
                float v0 = elu1(acc[i][j][0] + bias[cb]);
                float v1 = elu1(acc[i][j][1] + bias[cb + 1]);
                float v2 = elu1(acc[i][j][2] + bias[cb]);
                float v3 = elu1(acc[i][j][3] + bias[cb + 1]);
                if (u == 0) { hv.x = h2u2(v0, v1); hv.y = h2u2(v2, v3); }
                else        { hv.z = h2u2(v0, v1); hv.w = h2u2(v2, v3); }
                acc[i][j][0] = acc[i][j][1] = acc[i][j][2] = acc[i][j][3] = 0.f;
            }
            *(uint4*)(Af + ((i * 16 + wn * 2 + jp) * 32 + lane) * 16) = hv;
        }
    }
    __syncthreads();

    // layers 2 & 3
    #pragma unroll 1
    for (int layer = 1; layer <= 2; ++layer) {
        const int gbase = (layer == 1) ? 12 : 16;
        #pragma unroll 1
        for (int c = 0; c < 4; ++c) {
            const int gcw = gbase + c;
            uint2 B[4];
            ldgB(B, gcw, 0, wn, lane);
            #pragma unroll
            for (int ks = 0; ks < 4; ++ks) {
                uint2 Bn[4];
                if (ks < 3) ldgB(Bn, gcw, ks + 1, wn, lane);
                int sg = c * 4 + ks;
                #pragma unroll
                for (int half = 0; half < 2; ++half) {
                    uint4 A0 = *(const uint4*)(Af + (((half * 2 + 0) * 16 + sg) * 32 + lane) * 16);
                    uint4 A1 = *(const uint4*)(Af + (((half * 2 + 1) * 16 + sg) * 32 + lane) * 16);
                    #pragma unroll
                    for (int j = 0; j < 4; ++j) {
                        mma16816(acc[half * 2 + 0][j], A0.x, A0.y, A0.z, A0.w, B[j].x, B[j].y);
                        mma16816(acc[half * 2 + 1][j], A1.x, A1.y, A1.z, A1.w, B[j].x, B[j].y);
                    }
                }
                if (ks < 3) { B[0] = Bn[0]; B[1] = Bn[1]; B[2] = Bn[2]; B[3] = Bn[3]; }
            }
        }

        if (layer == 1) {
            __syncthreads();
            #pragma unroll
            for (int i = 0; i < 4; ++i) {
                #pragma unroll
                for (int jp = 0; jp < 2; ++jp) {
                    uint4 hv;
                    #pragma unroll
                    for (int u = 0; u < 2; ++u) {
                        int j = 2 * jp + u;
                        int cb = wn * 32 + j * 8 + tig * 2;
                        float v0 = elu1(acc[i][j][0] + bias[256 + cb]);
                        float v1 = elu1(acc[i][j][1] + bias[256 + cb + 1]);
                        float v2 = elu1(acc[i][j][2] + bias[256 + cb]);
                        float v3 = elu1(acc[i][j][3] + bias[256 + cb + 1]);
                        if (u == 0) { hv.x = h2u2(v0, v1); hv.y = h2u2(v2, v3); }
                        else        { hv.z = h2u2(v0, v1); hv.w = h2u2(v2, v3); }
                        acc[i][j][0] = acc[i][j][1] = acc[i][j][2] = acc[i][j][3] = 0.f;
                    }
                    *(uint4*)(Af + ((i * 16 + wn * 2 + jp) * 32 + lane) * 16) = hv;
                }
            }
            __syncthreads();
        }
    }

    // final epilogue: acc + b2 + E residual -> g_nodeH[node] (fp16 frag-major)
    #pragma unroll
    for (int i = 0; i < 4; ++i) {
        int r_g  = i * 16 + g;
        int r_g8 = r_g + 8;
        const float* e0p = rowptr[r_g];
        const float* e1p = rowptr[r_g8];
        #pragma unroll
        for (int j = 0; j < 4; ++j) {
            int cb = wn * 32 + j * 8 + tig * 2;
            float b0v = bias[512 + cb], b1v = bias[512 + cb + 1];
            float2 e0 = *(const float2*)(e0p + cb);
            float2 e1 = *(const float2*)(e1p + cb);
            float o0 = acc[i][j][0] + b0v + e0.x, o1 = acc[i][j][1] + b1v + e0.y;
            float o2 = acc[i][j][2] + b0v + e1.x, o3 = acc[i][j][3] + b1v + e1.y;
            int sg = wn * 2 + (j >> 1);
            int hoff = (j & 1) * 8;
            char* dst = (char*)(g_nodeH + (size_t)node * 2048 + (i * 16 + sg) * 32 + lane) + hoff;
            *(uint2*)dst = make_uint2(h2u2(o0, o1), h2u2(o2, o3));
        }
    }
}

// ================= tail: M-split full 3-layer fusion, ONE launch per level (<= 128) =================
__global__ void __launch_bounds__(256, 2)
tail_fused(const int* __restrict__ tokens, const float* __restrict__ E,
           const float* __restrict__ b_in, const float* __restrict__ b1,
           const float* __restrict__ b2, float* __restrict__ d_out, int level)
{
    extern __shared__ char smem[];
    float* bias = (float*)(smem + TF_BIAS);
    const float** rowptr = (const float**)(smem + TF_RPTR);
    const uint32_t sbA = smem_u32(smem);

    const int tid  = threadIdx.x;
    const int wn   = tid >> 5;
    const int lane = tid & 31;
    const int g    = lane >> 2;
    const int tig  = lane & 3;
    const int nloc   = blockIdx.x >> 2;
    const int mslice = blockIdx.x & 3;
    const int node   = level - 1 + nloc;

    bias[tid]       = b_in[tid];
    bias[256 + tid] = b1[tid];
    bias[512 + tid] = b2[tid];
    if (tid < 16)
        rowptr[tid] = E + (size_t)tokens[(mslice * 16 + tid) * NTOK + node] * D;

    // children slices -> smem[8192..24576) (raw fp16 frag copies)
    #pragma unroll
    for (int ch = 0; ch < 2; ++ch)
        #pragma unroll
        for (int rr = 0; rr < 2; ++rr) {
            int idx = rr * 256 + tid;                  // sg*32 + ln
            int sg = idx >> 5, ln = idx & 31;
            cp_async16(sbA + 8192 + ch * 8192 + (uint32_t)idx * 16,
                       (const void*)(g_nodeH + (size_t)(2 * node + 1 + ch) * 2048
                                     + (mslice * 16 + sg) * 32 + ln));
        }
    cp_commit();
    __syncthreads();   // rowptr visible

    {   // roots gather -> smem[0..8192)
        int sgi = tid >> 4, grg = (tid >> 2) & 3, gtig = tid & 3;
        const float* pr0 = rowptr[grg];
        const float* pr1 = rowptr[grg + 8];
        const float* pr2 = rowptr[grg + 4];
        const float* pr3 = rowptr[grg + 12];
        int kb = sgi * 16 + gtig * 2;
        float2 a0 = *(const float2*)(pr0 + kb),     a1 = *(const float2*)(pr1 + kb);
        float2 a2 = *(const float2*)(pr0 + kb + 8), a3 = *(const float2*)(pr1 + kb + 8);
        float2 c0 = *(const float2*)(pr2 + kb),     c1 = *(const float2*)(pr3 + kb);
        float2 c2 = *(const float2*)(pr2 + kb + 8), c3 = *(const float2*)(pr3 + kb + 8);
        uint4 h1v = make_uint4(h2u2(a0.x, a0.y), h2u2(a1.x, a1.y), h2u2(a2.x, a2.y), h2u2(a3.x, a3.y));
        uint4 h2v = make_uint4(h2u2(c0.x, c0.y), h2u2(c1.x, c1.y), h2u2(c2.x, c2.y), h2u2(c3.x, c3.y));
        char* base = smem + sgi * 512;
        *(uint4*)(base + (grg * 4 + gtig) * 16)       = h1v;
        *(uint4*)(base + ((grg + 4) * 4 + gtig) * 16) = h2v;
    }
    cp_wait<0>();
    __syncthreads();

    float acc[4][4];
    #pragma unroll
    for (int j = 0; j < 4; ++j)
        #pragma unroll
        for (int q = 0; q < 4; ++q) acc[j][q] = 0.f;

    const uint4* wb = (const uint4*)g_W4 + ((size_t)wn * 32 + lane) * 2;  // +ks*512

    // ---- layer 1: ks 0..47, A linear in smem ----
    uint4 B0 = wb[0], B1 = wb[1];
    #pragma unroll 4
    for (int ks = 0; ks < 48; ++ks) {
        uint4 Bn0, Bn1;
        if (ks < 47) { Bn0 = wb[(size_t)(ks + 1) * 512]; Bn1 = wb[(size_t)(ks + 1) * 512 + 1]; }
        uint4 A0 = *(const uint4*)(smem + ks * 512 + lane * 16);
        mma16816(acc[0], A0.x, A0.y, A0.z, A0.w, B0.x, B0.y);
        mma16816(acc[1], A0.x, A0.y, A0.z, A0.w, B0.z, B0.w);
        mma16816(acc[2], A0.x, A0.y, A0.z, A0.w, B1.x, B1.y);
        mma16816(acc[3], A0.x, A0.y, A0.z, A0.w, B1.z, B1.w);
        if (ks < 47) { B0 = Bn0; B1 = Bn1; }
    }

    // epi 1 -> Af
    #pragma unroll
    for (int jj = 0; jj < 4; ++jj) {
        int jt = wn * 4 + jj;
        int cb = jt * 8 + tig * 2;
        float v0 = elu1(acc[jj][0] + bias[cb]);
        float v1 = elu1(acc[jj][1] + bias[cb + 1]);
        float v2 = elu1(acc[jj][2] + bias[cb]);
        float v3 = elu1(acc[jj][3] + bias[cb + 1]);
        *(uint2*)(smem + TF_AF + (jt >> 1) * 512 + lane * 16 + (jt & 1) * 8)
            = make_uint2(h2u2(v0, v1), h2u2(v2, v3));
        acc[jj][0] = acc[jj][1] = acc[jj][2] = acc[jj][3] = 0.f;
    }
    __syncthreads();

    // ---- layer 2: ks 48..63, A = Af ----
    B0 = wb[(size_t)48 * 512]; B1 = wb[(size_t)48 * 512 + 1];
    #pragma unroll 4
    for (int k2 = 0; k2 < 16; ++k2) {
        uint4 Bn0, Bn1;
        if (k2 < 15) { Bn0 = wb[(size_t)(49 + k2) * 512]; Bn1 = wb[(size_t)(49 + k2) * 512 + 1]; }
        uint4 A0 = *(const uint4*)(smem + TF_AF + k2 * 512 + lane * 16);
        mma16816(acc[0], A0.x, A0.y, A0.z, A0.w, B0.x, B0.y);
        mma16816(acc[1], A0.x, A0.y, A0.z, A0.w, B0.z, B0.w);
        mma16816(acc[2], A0.x, A0.y, A0.z, A0.w, B1.x, B1.y);
        mma16816(acc[3], A0.x, A0.y, A0.z, A0.w, B1.z, B1.w);
        if (k2 < 15) { B0 = Bn0; B1 = Bn1; }
    }

    __syncthreads();   // all warps done reading Af before overwrite
    #pragma unroll
    for (int jj = 0; jj < 4; ++jj) {
        int jt = wn * 4 + jj;
        int cb = jt * 8 + tig * 2;
        float v0 = elu1(acc[jj][0] + bias[256 + cb]);
        float v1 = elu1(acc[jj][1] + bias[256 + cb + 1]);
        float v2 = elu1(acc[jj][2] + bias[256 + cb]);
        float v3 = elu1(acc[jj][3] + bias[256 + cb + 1]);
        *(uint2*)(smem + TF_AF + (jt >> 1) * 512 + lane * 16 + (jt & 1) * 8)
            = make_uint2(h2u2(v0, v1), h2u2(v2, v3));
        acc[jj][0] = acc[jj][1] = acc[jj][2] = acc[jj][3] = 0.f;
    }
    __syncthreads();

    // ---- layer 3: ks 64..79 ----
    B0 = wb[(size_t)64 * 512]; B1 = wb[(size_t)64 * 512 + 1];
    #pragma unroll 4
    for (int k3 = 0; k3 < 16; ++k3) {
        uint4 Bn0, Bn1;
        if (k3 < 15) { Bn0 = wb[(size_t)(65 + k3) * 512]; Bn1 = wb[(size_t)(65 + k3) * 512 + 1]; }
        uint4 A0 = *(const uint4*)(smem + TF_AF + k3 * 512 + lane * 16);
        mma16816(acc[0], A0.x, A0.y, A0.z, A0.w, B0.x, B0.y);
        mma16816(acc[1], A0.x, A0.y, A0.z, A0.w, B0.z, B0.w);
        mma16816(acc[2], A0.x, A0.y, A0.z, A0.w, B1.x, B1.y);
        mma16816(acc[3], A0.x, A0.y, A0.z, A0.w, B1.z, B1.w);
        if (k3 < 15) { B0 = Bn0; B1 = Bn1; }
    }

    // final epilogue: + b2 + E residual
    #pragma unroll
    for (int jj = 0; jj < 4; ++jj) {
        int jt = wn * 4 + jj;
        int cb = jt * 8 + tig * 2;
        float b0v = bias[512 + cb], b1v = bias[512 + cb + 1];
        float2 e0 = *(const float2*)(rowptr[g] + cb);
        float2 e1 = *(const float2*)(rowptr[g + 8] + cb);
        float o0 = acc[jj][0] + b0v + e0.x, o1 = acc[jj][1] + b1v + e0.y;
        float o2 = acc[jj][2] + b0v + e1.x, o3 = acc[jj][3] + b1v + e1.y;
        if (level == 1) {
            *(float2*)(d_out + (size_t)(mslice * 16 + g) * D + cb)     = make_float2(o0, o1);
            *(float2*)(d_out + (size_t)(mslice * 16 + g + 8) * D + cb) = make_float2(o2, o3);
        } else {
            char* dst = (char*)(g_nodeH + (size_t)node * 2048
                                + (mslice * 16 + (jt >> 1)) * 32 + lane) + (jt & 1) * 8;
            *(uint2*)dst = make_uint2(h2u2(o0, o1), h2u2(o2, o3));
        }
    }
}

extern "C" void kernel_launch(void* const* d_in, const int* in_sizes, int n_in,
                              void* d_out, int out_size) {
    const int*   tokens = (const int*)d_in[0];
    const float* E      = (const float*)d_in[1];
    const float* W_in   = (const float*)d_in[2];
    const float* b_in   = (const float*)d_in[3];
    const float* W1     = (const float*)d_in[4];
    const float* b1     = (const float*)d_in[5];
    const float* W2     = (const float*)d_in[6];
    const float* b2     = (const float*)d_in[7];
    float* out = (float*)d_out;

    cudaFuncSetAttribute(level_kernel, cudaFuncAttributeMaxDynamicSharedMemorySize, SMEM_TOTAL);
    cudaFuncSetAttribute(tail_fused,   cudaFuncAttributeMaxDynamicSharedMemorySize, TF_SMEM);

    prep_weights<<<(NCH * 4096) / 256, 256>>>(W_in, W1, W2);

    for (int level = 1024; level >= 256; level >>= 1)
        level_kernel<<<level, 256, SMEM_TOTAL>>>(tokens, E, b_in, b1, b2, level);

    for (int level = 128; level >= 1; level >>= 1)
        tail_fused<<<level * 4, 256, TF_SMEM>>>(tokens, E, b_in, b1, b2, out, level);
}